// round 1
// baseline (speedup 1.0000x reference)
#include <cuda_runtime.h>
#include <math.h>

// Problem constants
#define BD   4
#define LD   8192
#define CD   256
#define HID  2048
#define NS   16          // split-K chunks for the context GEMM
#define EPSL 1e-5f

// ---------------- scratch (__device__ globals; no allocations) ----------------
__device__ float g_Q[BD * LD * CD];
__device__ float g_K[BD * LD * CD];
__device__ float g_V[BD * LD * CD];
__device__ float g_colsum[BD * CD];
__device__ float g_ctxpart[BD * NS * CD * CD];
__device__ float g_ctx[BD * CD * CD];
__device__ float g_Mm[BD * CD * CD];
__device__ float g_attn[BD * LD * CD];
__device__ float g_hidden[BD * LD * HID];     // 268 MB
__device__ float g_tmp2[BD * LD * CD];

// ---------------- generic 128x128x8 fp32 GEMM, 8x8 microtile ----------------
// AMODE: 0 = A row-major (m,k)=A[m*lda+k]
//        1 = A "transposed" access (m,k)=A[k*lda+m]   (for Q^T K and ctx^T Wl)
//        2 = concat A: k<256 -> A[m*256+k], else A2[m*256+(k-256)]
// EPI:   0 = store, 1 = +bias, 2 = +bias then exact GELU
// All M,N multiples of 128; all K (and K/nsplit) multiples of 8. No bounds checks.
template <int AMODE, int EPI>
__global__ void gemm_k(const float* __restrict__ A, const float* __restrict__ A2,
                       const float* __restrict__ Bm, const float* __restrict__ bias,
                       float* __restrict__ Cmat,
                       int Kd, int nsplit,
                       int lda, int ldb, int ldc,
                       long long sA, long long sB, long long sC)
{
    const int z = blockIdx.z;
    const int b = z / nsplit;
    const int s = z - b * nsplit;
    const float* Ab = A + (long long)b * sA;
    const float* Bb = Bm + (long long)b * sB;
    float* Cb = Cmat + (long long)z * sC;

    const int kChunk = Kd / nsplit;
    const int k0 = s * kChunk;
    const int k1 = k0 + kChunk;

    const int m0 = blockIdx.y * 128;
    const int n0 = blockIdx.x * 128;

    __shared__ float As[8][128];
    __shared__ float Bs[8][128];

    const int tid = threadIdx.x;
    const int ty = tid >> 4;          // 0..15
    const int tx = tid & 15;          // 0..15

    float acc[8][8];
#pragma unroll
    for (int i = 0; i < 8; i++)
#pragma unroll
        for (int j = 0; j < 8; j++) acc[i][j] = 0.0f;

    for (int kt = k0; kt < k1; kt += 8) {
        // ---- load A tile into As[k][m] ----
        if (AMODE == 1) {
            const int kr = tid >> 5;              // 0..7
            const int mc = (tid & 31) * 4;        // 0..124
            float4 a = *(const float4*)&Ab[(size_t)(kt + kr) * lda + m0 + mc];
            *(float4*)&As[kr][mc] = a;
        } else {
            const int ar = tid >> 1;              // 0..127
            const int ac = (tid & 1) * 4;         // 0 or 4
            const int kk = kt + ac;
            const float* src;
            if (AMODE == 2) {
                if (kk >= CD) src = &A2[(size_t)(m0 + ar) * CD + (kk - CD)];
                else          src = &Ab[(size_t)(m0 + ar) * CD + kk];
            } else {
                src = &Ab[(size_t)(m0 + ar) * lda + kk];
            }
            float4 a = *(const float4*)src;
            As[ac + 0][ar] = a.x;
            As[ac + 1][ar] = a.y;
            As[ac + 2][ar] = a.z;
            As[ac + 3][ar] = a.w;
        }
        // ---- load B tile into Bs[k][n] ----
        {
            const int kr = tid >> 5;
            const int nc = (tid & 31) * 4;
            *(float4*)&Bs[kr][nc] = *(const float4*)&Bb[(size_t)(kt + kr) * ldb + n0 + nc];
        }
        __syncthreads();

#pragma unroll
        for (int k = 0; k < 8; k++) {
            float a[8], bb[8];
            *(float4*)&a[0]  = *(const float4*)&As[k][ty * 8];
            *(float4*)&a[4]  = *(const float4*)&As[k][ty * 8 + 4];
            *(float4*)&bb[0] = *(const float4*)&Bs[k][tx * 8];
            *(float4*)&bb[4] = *(const float4*)&Bs[k][tx * 8 + 4];
#pragma unroll
            for (int i = 0; i < 8; i++)
#pragma unroll
                for (int j = 0; j < 8; j++)
                    acc[i][j] = fmaf(a[i], bb[j], acc[i][j]);
        }
        __syncthreads();
    }

    // ---- epilogue ----
#pragma unroll
    for (int i = 0; i < 8; i++) {
        const int row = m0 + ty * 8 + i;
#pragma unroll
        for (int j = 0; j < 8; j++) {
            const int col = n0 + tx * 8 + j;
            float v = acc[i][j];
            if (EPI >= 1) v += bias[col];
            if (EPI == 2) v = 0.5f * v * (1.0f + erff(v * 0.70710678118654752f));
            Cb[(size_t)row * ldc + col] = v;
        }
    }
}

// ---------------- column softmax of K over the token dim (in place -> exp(k-max)),
// writes per-column sum to colsum. Block = (32 channels, 32 token-lanes). -------
__global__ void softmax_cols(float* __restrict__ Kp, float* __restrict__ colsum)
{
    const int bc = blockIdx.x;                 // B * (C/32)
    const int b  = bc / (CD / 32);
    const int cg = bc - b * (CD / 32);
    const int tx = threadIdx.x, ty = threadIdx.y;
    const int c  = cg * 32 + tx;
    float* Kb = Kp + (size_t)b * LD * CD + c;

    __shared__ float red[32][33];

    float m = -INFINITY;
    for (int l = ty; l < LD; l += 32)
        m = fmaxf(m, Kb[(size_t)l * CD]);
    red[ty][tx] = m;
    __syncthreads();
    for (int sft = 16; sft > 0; sft >>= 1) {
        if (ty < sft) red[ty][tx] = fmaxf(red[ty][tx], red[ty + sft][tx]);
        __syncthreads();
    }
    m = red[0][tx];
    __syncthreads();

    float sum = 0.0f;
    for (int l = ty; l < LD; l += 32) {
        float e = expf(Kb[(size_t)l * CD] - m);
        Kb[(size_t)l * CD] = e;
        sum += e;
    }
    red[ty][tx] = sum;
    __syncthreads();
    for (int sft = 16; sft > 0; sft >>= 1) {
        if (ty < sft) red[ty][tx] += red[ty + sft][tx];
        __syncthreads();
    }
    if (ty == 0) colsum[b * CD + c] = red[0][tx];
}

// ---------------- reduce split-K context partials; fold 1/colsum[e] ----------
__global__ void ctx_reduce(const float* __restrict__ part,
                           const float* __restrict__ colsum,
                           float* __restrict__ ctx)
{
    const int idx = blockIdx.x * 256 + threadIdx.x;   // < B*C*C
    const int b  = idx / (CD * CD);
    const int de = idx - b * (CD * CD);
    const int e  = de & (CD - 1);
    float s = 0.0f;
#pragma unroll
    for (int p = 0; p < NS; p++)
        s += part[((size_t)b * NS + p) * CD * CD + de];
    ctx[idx] = s / colsum[b * CD + e];
}

// ---------------- row LayerNorm over C=256: one warp per row ----------------
// addRes=1: out = src + LN(x); addRes=0: out = LN(x) (in-place safe)
__global__ void ln_rows(const float* __restrict__ X, const float* __restrict__ src,
                        const float* __restrict__ gamma, const float* __restrict__ beta,
                        float* __restrict__ out, int addRes)
{
    const int row  = blockIdx.x * 8 + threadIdx.y;     // B*L rows
    const int lane = threadIdx.x;
    const float* x = X + (size_t)row * CD;

    float v[8];
#pragma unroll
    for (int i = 0; i < 8; i++) v[i] = x[lane + i * 32];

    float s = 0.0f;
#pragma unroll
    for (int i = 0; i < 8; i++) s += v[i];
#pragma unroll
    for (int o = 16; o > 0; o >>= 1) s += __shfl_xor_sync(0xffffffffu, s, o);
    const float mu = s * (1.0f / CD);

    float q = 0.0f;
#pragma unroll
    for (int i = 0; i < 8; i++) { float d = v[i] - mu; q += d * d; }
#pragma unroll
    for (int o = 16; o > 0; o >>= 1) q += __shfl_xor_sync(0xffffffffu, q, o);
    const float rstd = rsqrtf(q * (1.0f / CD) + EPSL);

#pragma unroll
    for (int i = 0; i < 8; i++) {
        const int c = lane + i * 32;
        float y = (v[i] - mu) * rstd * gamma[c] + beta[c];
        if (addRes) y += src[(size_t)row * CD + c];
        out[(size_t)row * CD + c] = y;
    }
}

// ---------------- launcher ----------------
extern "C" void kernel_launch(void* const* d_in, const int* in_sizes, int n_in,
                              void* d_out, int out_size)
{
    const float* source = (const float*)d_in[0];
    const float* target = (const float*)d_in[1];
    const float* Wq     = (const float*)d_in[2];
    const float* Wk     = (const float*)d_in[3];
    const float* Wv     = (const float*)d_in[4];
    const float* Wl     = (const float*)d_in[5];
    const float* gamma1 = (const float*)d_in[6];
    const float* beta1  = (const float*)d_in[7];
    const float* W1     = (const float*)d_in[8];
    const float* b1     = (const float*)d_in[9];
    const float* W2     = (const float*)d_in[10];
    const float* b2     = (const float*)d_in[11];
    const float* gamma2 = (const float*)d_in[12];
    const float* beta2  = (const float*)d_in[13];
    // d_in[14], d_in[15] = h, w (unused; L = h*w fixed)

    float *Q, *Kb, *V, *colsum, *ctxpart, *ctx, *Mm, *attn, *hidden, *tmp2;
    cudaGetSymbolAddress((void**)&Q,       g_Q);
    cudaGetSymbolAddress((void**)&Kb,      g_K);
    cudaGetSymbolAddress((void**)&V,       g_V);
    cudaGetSymbolAddress((void**)&colsum,  g_colsum);
    cudaGetSymbolAddress((void**)&ctxpart, g_ctxpart);
    cudaGetSymbolAddress((void**)&ctx,     g_ctx);
    cudaGetSymbolAddress((void**)&Mm,      g_Mm);
    cudaGetSymbolAddress((void**)&attn,    g_attn);
    cudaGetSymbolAddress((void**)&hidden,  g_hidden);
    cudaGetSymbolAddress((void**)&tmp2,    g_tmp2);

    const long long LC = (long long)LD * CD;
    const long long CC = (long long)CD * CD;

    // 1-3) Q = source@Wq ; Kraw = target@Wk ; V = target@Wv   (M=32768,N=256,K=256)
    gemm_k<0, 0><<<dim3(2, 256, 1), 256>>>(source, nullptr, Wq, nullptr, Q,
                                           CD, 1, CD, CD, CD, 0, 0, 0);
    gemm_k<0, 0><<<dim3(2, 256, 1), 256>>>(target, nullptr, Wk, nullptr, Kb,
                                           CD, 1, CD, CD, CD, 0, 0, 0);
    gemm_k<0, 0><<<dim3(2, 256, 1), 256>>>(target, nullptr, Wv, nullptr, V,
                                           CD, 1, CD, CD, CD, 0, 0, 0);

    // 4) column softmax of K over tokens: K <- exp(K - colmax), colsum
    softmax_cols<<<BD * (CD / 32), dim3(32, 32)>>>(Kb, colsum);

    // 5) context partials: ctxpart[b][s] = Q[b]^T (L-chunk s) @ expK[b]
    gemm_k<1, 0><<<dim3(2, 2, BD * NS), 256>>>(Q, nullptr, Kb, nullptr, ctxpart,
                                               LD, NS, CD, CD, CD, LC, LC, CC);

    // 6) ctx[b] = (sum over splits) / colsum[e]
    ctx_reduce<<<BD * CD * CD / 256, 256>>>(ctxpart, colsum, ctx);

    // 7) Mm[b] = ctx[b]^T @ Wl   (folds attn@Wl into one small GEMM)
    gemm_k<1, 0><<<dim3(2, 2, BD), 256>>>(ctx, nullptr, Wl, nullptr, Mm,
                                          CD, 1, CD, CD, CD, CC, 0, CC);

    // 8) attn[b] = V[b] @ Mm[b]   (M=8192 per batch, N=256, K=256)
    gemm_k<0, 0><<<dim3(2, 64, BD), 256>>>(V, nullptr, Mm, nullptr, attn,
                                           CD, 1, CD, CD, CD, LC, CC, LC);

    // 9) message = LN(attn) with gamma1/beta1  (in place)
    ln_rows<<<BD * LD / 8, dim3(32, 8)>>>(attn, nullptr, gamma1, beta1, attn, 0);

    // 10) hidden = gelu([source, message] @ W1 + b1)   (M=32768,N=2048,K=512)
    gemm_k<2, 2><<<dim3(16, 256, 1), 256>>>(source, attn, W1, b1, hidden,
                                            2 * CD, 1, CD, HID, HID, 0, 0, 0);

    // 11) tmp2 = hidden @ W2 + b2   (M=32768,N=256,K=2048)
    gemm_k<0, 1><<<dim3(2, 256, 1), 256>>>(hidden, nullptr, W2, b2, tmp2,
                                           HID, 1, HID, CD, CD, 0, 0, 0);

    // 12) out = source + LN(tmp2) with gamma2/beta2
    ln_rows<<<BD * LD / 8, dim3(32, 8)>>>(tmp2, source, gamma2, beta2,
                                          (float*)d_out, 1);
}

// round 3
// speedup vs baseline: 1.1512x; 1.1512x over previous
#include <cuda_runtime.h>
#include <math.h>
#include <stdint.h>

// Problem constants
#define BD   4
#define LD   8192
#define CD   256
#define HID  2048
#define NS   16
#define EPSL 1e-5f

// ---------------- scratch (__device__ globals; no allocations) ----------------
__device__ float g_Q[BD * LD * CD];
__device__ float g_K[BD * LD * CD];
__device__ float g_V[BD * LD * CD];
__device__ float g_colsum[BD * CD];
__device__ float g_ctxpart[BD * NS * CD * CD];
__device__ float g_ctx[BD * CD * CD];
__device__ float g_Mm[BD * CD * CD];
__device__ float g_attn[BD * LD * CD];
__device__ float g_hidden[BD * LD * HID];
__device__ float g_tmp2[BD * LD * CD];

// ---------------- helpers ----------------
__device__ __forceinline__ uint32_t f2tf(float f) {
    uint32_t r; asm("cvt.rna.tf32.f32 %0, %1;" : "=r"(r) : "f"(f)); return r;
}

__device__ __forceinline__ void mma_tf32(float* c, const uint32_t* a, const uint32_t* b) {
    asm volatile(
        "mma.sync.aligned.m16n8k8.row.col.f32.tf32.tf32.f32 "
        "{%0,%1,%2,%3}, {%4,%5,%6,%7}, {%8,%9}, {%0,%1,%2,%3};"
        : "+f"(c[0]), "+f"(c[1]), "+f"(c[2]), "+f"(c[3])
        : "r"(a[0]), "r"(a[1]), "r"(a[2]), "r"(a[3]), "r"(b[0]), "r"(b[1]));
}

// ---------------- tf32 mma.sync GEMM ----------------
// CTA tile 128x128x32; 8 warps (2 m x 4 n), warp tile 64x32.
// SMEM holds operands pre-permuted into mma fragment layout:
//   A area (words): ((kstep*8 + mtile)*32 + lane)*4 + slot   (4 k-steps, 8 m-tiles of 16x8)
//     slot: 0=A[g,t] 1=A[g+8,t] 2=A[g,t+4] 3=A[g+8,t+4], lane=(r&7)*4+(c&3)
//   B area (words): ((kstep*16 + ntile)*32 + lane)*2 + slot  (16 n-tiles of 8(k)x8(n))
//     slot: 0=B[t,g] 1=B[t+4,g], lane=(n&7)*4+(k&3)
// AMODE: 0 row-major A; 1 transposed A ((m,k)=A[k*lda+m]); 2 concat [A|A2] (K=512)
// EPI: 0 store; 1 +bias; 2 +bias then exact GELU
#define BM 128
#define BN 128
#define BK 32
#define AWORDS 4096
#define BWORDS 4096
#define BUFWORDS 8192
#define SMEM_TOTAL 65536

template <int AMODE, int EPI>
__global__ void __launch_bounds__(256)
tgemm(const float* __restrict__ A, const float* __restrict__ A2,
      const float* __restrict__ Bm, const float* __restrict__ bias,
      float* __restrict__ Cmat,
      int Kd, int nsplit, int lda, int ldb, int ldc,
      long long sA, long long sB, long long sC)
{
    extern __shared__ uint32_t sm[];
    const int tid = threadIdx.x;
    const int wid = tid >> 5, lane = tid & 31;
    const int wm = wid >> 2;              // 0..1  (m direction)
    const int wn = wid & 3;               // 0..3  (n direction)

    const int z = blockIdx.z;
    const int b = z / nsplit;
    const int s = z - b * nsplit;
    const float* Ab = A + (long long)b * sA;
    const float* Bb = Bm + (long long)b * sB;
    float* Cb = Cmat + (long long)z * sC;
    const int kChunk = Kd / nsplit;
    const int k0 = s * kChunk;
    const int T = kChunk / BK;
    const int m0 = blockIdx.y * BM;
    const int n0 = blockIdx.x * BN;

    float4 ra[4], rb[4];

    auto loadTiles = [&](int kt) {
#pragma unroll
        for (int j = 0; j < 4; j++) {
            const int idx = tid + 256 * j;
            if (AMODE == 1) {
                const int k = idx >> 5, mq = idx & 31;
                ra[j] = *(const float4*)&Ab[(size_t)(kt + k) * lda + m0 + mq * 4];
            } else {
                const int m = idx >> 3, f4 = idx & 7;
                const int kk = kt + f4 * 4;
                const float* src;
                if (AMODE == 2)
                    src = (kk < CD) ? &Ab[(size_t)(m0 + m) * CD + kk]
                                    : &A2[(size_t)(m0 + m) * CD + (kk - CD)];
                else
                    src = &Ab[(size_t)(m0 + m) * lda + kk];
                ra[j] = *(const float4*)src;
            }
        }
#pragma unroll
        for (int j = 0; j < 4; j++) {
            const int idx = tid + 256 * j;
            const int kr = idx >> 5, nq = idx & 31;
            rb[j] = *(const float4*)&Bb[(size_t)(kt + kr) * ldb + n0 + nq * 4];
        }
    };

    auto stsTiles = [&](int buf) {
        uint32_t* Aw = sm + buf * BUFWORDS;
        uint32_t* Bw = Aw + AWORDS;
#pragma unroll
        for (int j = 0; j < 4; j++) {
            const int idx = tid + 256 * j;
            float v[4] = {ra[j].x, ra[j].y, ra[j].z, ra[j].w};
            if (AMODE == 1) {
                const int k = idx >> 5, mq = idx & 31;
                const int kstep = k >> 3, kk = k & 7;
                const int slot2 = ((kk >> 2) & 1) * 2;
#pragma unroll
                for (int e = 0; e < 4; e++) {
                    const int m = mq * 4 + e;
                    const int r = m & 15, mtile = m >> 4;
                    const int ln = (r & 7) * 4 + (kk & 3);
                    const int slot = (r >> 3) + slot2;
                    Aw[((kstep * 8 + mtile) * 32 + ln) * 4 + slot] = f2tf(v[e]);
                }
            } else {
                const int m = idx >> 3, f4 = idx & 7;
                const int kstep = f4 >> 1;
                const int r = m & 15, mtile = m >> 4;
                const int slot2 = (f4 & 1) * 2;
                const int hi = r >> 3;
                const int lnb = (r & 7) * 4;
#pragma unroll
                for (int e = 0; e < 4; e++)
                    Aw[((kstep * 8 + mtile) * 32 + lnb + e) * 4 + hi + slot2] = f2tf(v[e]);
            }
        }
#pragma unroll
        for (int j = 0; j < 4; j++) {
            const int idx = tid + 256 * j;
            const int kr = idx >> 5, nq = idx & 31;
            const int kstep = kr >> 3, kk = kr & 7;
            const int slot = kk >> 2;
            float v[4] = {rb[j].x, rb[j].y, rb[j].z, rb[j].w};
#pragma unroll
            for (int e = 0; e < 4; e++) {
                const int n = nq * 4 + e;
                const int ntile = n >> 3, c = n & 7;
                const int ln = c * 4 + (kk & 3);
                Bw[((kstep * 16 + ntile) * 32 + ln) * 2 + slot] = f2tf(v[e]);
            }
        }
    };

    float acc[4][4][4];
#pragma unroll
    for (int i = 0; i < 4; i++)
#pragma unroll
        for (int j = 0; j < 4; j++)
#pragma unroll
            for (int e = 0; e < 4; e++) acc[i][j][e] = 0.0f;

    // prologue
    loadTiles(k0);
    stsTiles(0);
    __syncthreads();

    for (int it = 0; it < T; ++it) {
        const int cur = it & 1;
        if (it + 1 < T) loadTiles(k0 + (it + 1) * BK);

        const uint32_t* Aw = sm + cur * BUFWORDS;
        const uint32_t* Bw = Aw + AWORDS;
#pragma unroll
        for (int ks = 0; ks < 4; ks++) {
            uint32_t af[4][4], bf[4][2];
#pragma unroll
            for (int i = 0; i < 4; i++) {
                const uint4 v = *(const uint4*)&Aw[((ks * 8 + wm * 4 + i) * 32 + lane) * 4];
                af[i][0] = v.x; af[i][1] = v.y; af[i][2] = v.z; af[i][3] = v.w;
            }
#pragma unroll
            for (int j = 0; j < 4; j++) {
                const uint2 v = *(const uint2*)&Bw[((ks * 16 + wn * 4 + j) * 32 + lane) * 2];
                bf[j][0] = v.x; bf[j][1] = v.y;
            }
#pragma unroll
            for (int i = 0; i < 4; i++)
#pragma unroll
                for (int j = 0; j < 4; j++)
                    mma_tf32(acc[i][j], af[i], bf[j]);
        }

        if (it + 1 < T) stsTiles((it + 1) & 1);
        __syncthreads();
    }

    // ---- epilogue: reg -> gmem, fused bias/GELU ----
    const int gid = lane >> 2, tig = lane & 3;
#pragma unroll
    for (int i = 0; i < 4; i++) {
        const int rbase = m0 + wm * 64 + i * 16 + gid;
#pragma unroll
        for (int j = 0; j < 4; j++) {
            const int cn = n0 + wn * 32 + j * 8 + tig * 2;
            float bia0 = 0.f, bia1 = 0.f;
            if (EPI >= 1) { bia0 = bias[cn]; bia1 = bias[cn + 1]; }
#pragma unroll
            for (int h = 0; h < 2; h++) {
                const int row = rbase + h * 8;
                float v0 = acc[i][j][2 * h + 0] + bia0;
                float v1 = acc[i][j][2 * h + 1] + bia1;
                if (EPI == 2) {
                    v0 = 0.5f * v0 * (1.0f + erff(v0 * 0.70710678118654752f));
                    v1 = 0.5f * v1 * (1.0f + erff(v1 * 0.70710678118654752f));
                }
                float2 out; out.x = v0; out.y = v1;
                *(float2*)&Cb[(size_t)row * ldc + cn] = out;
            }
        }
    }
}

// ---------------- column softmax of K over token dim ----------------
__global__ void softmax_cols(float* __restrict__ Kp, float* __restrict__ colsum)
{
    const int bc = blockIdx.x;
    const int b  = bc / (CD / 32);
    const int cg = bc - b * (CD / 32);
    const int tx = threadIdx.x, ty = threadIdx.y;
    const int c  = cg * 32 + tx;
    float* Kb = Kp + (size_t)b * LD * CD + c;

    __shared__ float red[32][33];

    float m = -INFINITY;
    for (int l = ty; l < LD; l += 32)
        m = fmaxf(m, Kb[(size_t)l * CD]);
    red[ty][tx] = m;
    __syncthreads();
    for (int sft = 16; sft > 0; sft >>= 1) {
        if (ty < sft) red[ty][tx] = fmaxf(red[ty][tx], red[ty + sft][tx]);
        __syncthreads();
    }
    m = red[0][tx];
    __syncthreads();

    float sum = 0.0f;
    for (int l = ty; l < LD; l += 32) {
        float e = expf(Kb[(size_t)l * CD] - m);
        Kb[(size_t)l * CD] = e;
        sum += e;
    }
    red[ty][tx] = sum;
    __syncthreads();
    for (int sft = 16; sft > 0; sft >>= 1) {
        if (ty < sft) red[ty][tx] += red[ty + sft][tx];
        __syncthreads();
    }
    if (ty == 0) colsum[b * CD + c] = red[0][tx];
}

// ---------------- reduce split-K context partials; fold 1/colsum ----------
__global__ void ctx_reduce(const float* __restrict__ part,
                           const float* __restrict__ colsum,
                           float* __restrict__ ctx)
{
    const int idx = blockIdx.x * 256 + threadIdx.x;
    const int b  = idx / (CD * CD);
    const int de = idx - b * (CD * CD);
    const int e  = de & (CD - 1);
    float s = 0.0f;
#pragma unroll
    for (int p = 0; p < NS; p++)
        s += part[((size_t)b * NS + p) * CD * CD + de];
    ctx[idx] = s / colsum[b * CD + e];
}

// ---------------- row LayerNorm over C=256 ----------------
__global__ void ln_rows(const float* __restrict__ X, const float* __restrict__ src,
                        const float* __restrict__ gamma, const float* __restrict__ beta,
                        float* __restrict__ out, int addRes)
{
    const int row  = blockIdx.x * 8 + threadIdx.y;
    const int lane = threadIdx.x;
    const float* x = X + (size_t)row * CD;

    float v[8];
#pragma unroll
    for (int i = 0; i < 8; i++) v[i] = x[lane + i * 32];

    float s = 0.0f;
#pragma unroll
    for (int i = 0; i < 8; i++) s += v[i];
#pragma unroll
    for (int o = 16; o > 0; o >>= 1) s += __shfl_xor_sync(0xffffffffu, s, o);
    const float mu = s * (1.0f / CD);

    float q = 0.0f;
#pragma unroll
    for (int i = 0; i < 8; i++) { float d = v[i] - mu; q += d * d; }
#pragma unroll
    for (int o = 16; o > 0; o >>= 1) q += __shfl_xor_sync(0xffffffffu, q, o);
    const float rstd = rsqrtf(q * (1.0f / CD) + EPSL);

#pragma unroll
    for (int i = 0; i < 8; i++) {
        const int c = lane + i * 32;
        float y = (v[i] - mu) * rstd * gamma[c] + beta[c];
        if (addRes) y += src[(size_t)row * CD + c];
        out[(size_t)row * CD + c] = y;
    }
}

// ---------------- launcher ----------------
extern "C" void kernel_launch(void* const* d_in, const int* in_sizes, int n_in,
                              void* d_out, int out_size)
{
    const float* source = (const float*)d_in[0];
    const float* target = (const float*)d_in[1];
    const float* Wq     = (const float*)d_in[2];
    const float* Wk     = (const float*)d_in[3];
    const float* Wv     = (const float*)d_in[4];
    const float* Wl     = (const float*)d_in[5];
    const float* gamma1 = (const float*)d_in[6];
    const float* beta1  = (const float*)d_in[7];
    const float* W1     = (const float*)d_in[8];
    const float* b1     = (const float*)d_in[9];
    const float* W2     = (const float*)d_in[10];
    const float* b2     = (const float*)d_in[11];
    const float* gamma2 = (const float*)d_in[12];
    const float* beta2  = (const float*)d_in[13];

    float *Q, *Kb, *V, *colsum, *ctxpart, *ctx, *Mm, *attn, *hidden, *tmp2;
    cudaGetSymbolAddress((void**)&Q,       g_Q);
    cudaGetSymbolAddress((void**)&Kb,      g_K);
    cudaGetSymbolAddress((void**)&V,       g_V);
    cudaGetSymbolAddress((void**)&colsum,  g_colsum);
    cudaGetSymbolAddress((void**)&ctxpart, g_ctxpart);
    cudaGetSymbolAddress((void**)&ctx,     g_ctx);
    cudaGetSymbolAddress((void**)&Mm,      g_Mm);
    cudaGetSymbolAddress((void**)&attn,    g_attn);
    cudaGetSymbolAddress((void**)&hidden,  g_hidden);
    cudaGetSymbolAddress((void**)&tmp2,    g_tmp2);

    cudaFuncSetAttribute(tgemm<0, 0>, cudaFuncAttributeMaxDynamicSharedMemorySize, SMEM_TOTAL);
    cudaFuncSetAttribute(tgemm<1, 0>, cudaFuncAttributeMaxDynamicSharedMemorySize, SMEM_TOTAL);
    cudaFuncSetAttribute(tgemm<2, 2>, cudaFuncAttributeMaxDynamicSharedMemorySize, SMEM_TOTAL);
    cudaFuncSetAttribute(tgemm<0, 1>, cudaFuncAttributeMaxDynamicSharedMemorySize, SMEM_TOTAL);

    const long long LC = (long long)LD * CD;
    const long long CC = (long long)CD * CD;

    // 1-3) Q/K/V projections (M=32768, N=256, K=256)
    tgemm<0, 0><<<dim3(2, 256, 1), 256, SMEM_TOTAL>>>(source, nullptr, Wq, nullptr, Q,
                                                      CD, 1, CD, CD, CD, 0, 0, 0);
    tgemm<0, 0><<<dim3(2, 256, 1), 256, SMEM_TOTAL>>>(target, nullptr, Wk, nullptr, Kb,
                                                      CD, 1, CD, CD, CD, 0, 0, 0);
    tgemm<0, 0><<<dim3(2, 256, 1), 256, SMEM_TOTAL>>>(target, nullptr, Wv, nullptr, V,
                                                      CD, 1, CD, CD, CD, 0, 0, 0);

    // 4) column softmax over tokens
    softmax_cols<<<BD * (CD / 32), dim3(32, 32)>>>(Kb, colsum);

    // 5) context partials: ctxpart[b][s] = Q^T(chunk) @ expK
    tgemm<1, 0><<<dim3(2, 2, BD * NS), 256, SMEM_TOTAL>>>(Q, nullptr, Kb, nullptr, ctxpart,
                                                          LD, NS, CD, CD, CD, LC, LC, CC);

    // 6) reduce + 1/colsum
    ctx_reduce<<<BD * CD * CD / 256, 256>>>(ctxpart, colsum, ctx);

    // 7) Mm = ctx^T @ Wl
    tgemm<1, 0><<<dim3(2, 2, BD), 256, SMEM_TOTAL>>>(ctx, nullptr, Wl, nullptr, Mm,
                                                     CD, 1, CD, CD, CD, CC, 0, CC);

    // 8) attn = V @ Mm
    tgemm<0, 0><<<dim3(2, 64, BD), 256, SMEM_TOTAL>>>(V, nullptr, Mm, nullptr, attn,
                                                      CD, 1, CD, CD, CD, LC, CC, LC);

    // 9) message = LN(attn)
    ln_rows<<<BD * LD / 8, dim3(32, 8)>>>(attn, nullptr, gamma1, beta1, attn, 0);

    // 10) hidden = gelu([source, message] @ W1 + b1)
    tgemm<2, 2><<<dim3(16, 256, 1), 256, SMEM_TOTAL>>>(source, attn, W1, b1, hidden,
                                                       2 * CD, 1, CD, HID, HID, 0, 0, 0);

    // 11) tmp2 = hidden @ W2 + b2
    tgemm<0, 1><<<dim3(2, 256, 1), 256, SMEM_TOTAL>>>(hidden, nullptr, W2, b2, tmp2,
                                                      HID, 1, HID, CD, CD, 0, 0, 0);

    // 12) out = source + LN(tmp2)
    ln_rows<<<BD * LD / 8, dim3(32, 8)>>>(tmp2, source, gamma2, beta2,
                                          (float*)d_out, 1);
}

// round 4
// speedup vs baseline: 2.7978x; 2.4303x over previous
#include <cuda_runtime.h>
#include <math.h>
#include <stdint.h>

// Problem constants
#define BD   4
#define LD   8192
#define CD   256
#define HID  2048
#define NS   16
#define EPSL 1e-5f

// ---------------- scratch (__device__ globals; no allocations) ----------------
__device__ float g_Q[BD * LD * CD];
__device__ float g_K[BD * LD * CD];
__device__ float g_V[BD * LD * CD];
__device__ float g_colsum[BD * CD];
__device__ float g_ctxpart[BD * NS * CD * CD];
__device__ float g_ctx[BD * CD * CD];
__device__ float g_Mm[BD * CD * CD];
__device__ float g_attn[BD * LD * CD];
__device__ float g_hidden[BD * LD * HID];
__device__ float g_tmp2[BD * LD * CD];

// ---------------- helpers ----------------
__device__ __forceinline__ uint32_t f2tf(float f) {
    uint32_t r; asm("cvt.rna.tf32.f32 %0, %1;" : "=r"(r) : "f"(f)); return r;
}

__device__ __forceinline__ void mma_tf32(float* c, const uint32_t* a, const uint32_t* b) {
    asm volatile(
        "mma.sync.aligned.m16n8k8.row.col.f32.tf32.tf32.f32 "
        "{%0,%1,%2,%3}, {%4,%5,%6,%7}, {%8,%9}, {%0,%1,%2,%3};"
        : "+f"(c[0]), "+f"(c[1]), "+f"(c[2]), "+f"(c[3])
        : "r"(a[0]), "r"(a[1]), "r"(a[2]), "r"(a[3]), "r"(b[0]), "r"(b[1]));
}

// ---------------- tf32 mma.sync GEMM ----------------
// CTA tile 128x128x32; 8 warps (2 m x 4 n), warp tile 64x32.
// SMEM natural layouts with xor swizzle (all hot LDS/STS bank-conflict-free):
//   A: word(m,k) = m*32 + (k ^ ((m&7)<<2))     (128 rows x 32 kwords)
//   B: word(k,n) = k*128 + (n ^ ((k&3)<<3))    (32 krows x 128 nwords)
// AMODE: 0 row-major A; 1 transposed A ((m,k)=A[k*lda+m]); 2 concat [A|A2] (K=512)
// EPI: 0 store; 1 +bias; 2 +bias then exact GELU
#define BM 128
#define BN 128
#define BK 32
#define AWORDS 4096
#define BUFWORDS 8192
#define SMEM_TOTAL 65536

template <int AMODE, int EPI>
__global__ void __launch_bounds__(256)
tgemm(const float* __restrict__ A, const float* __restrict__ A2,
      const float* __restrict__ Bm, const float* __restrict__ bias,
      float* __restrict__ Cmat,
      int Kd, int nsplit, int lda, int ldb, int ldc,
      long long sA, long long sB, long long sC)
{
    extern __shared__ uint32_t sm[];
    const int tid = threadIdx.x;
    const int wid = tid >> 5, lane = tid & 31;
    const int wm = wid >> 2;              // 0..1  (m direction)
    const int wn = wid & 3;               // 0..3  (n direction)
    const int gid = lane >> 2, tig = lane & 3;

    const int z = blockIdx.z;
    const int b = z / nsplit;
    const int s = z - b * nsplit;
    const float* Ab = A + (long long)b * sA;
    const float* Bb = Bm + (long long)b * sB;
    float* Cb = Cmat + (long long)z * sC;
    const int kChunk = Kd / nsplit;
    const int k0 = s * kChunk;
    const int T = kChunk / BK;
    const int m0 = blockIdx.y * BM;
    const int n0 = blockIdx.x * BN;

    float4 ra[4], rb[4];

    auto loadTiles = [&](int kt) {
#pragma unroll
        for (int j = 0; j < 4; j++) {
            const int idx = tid + 256 * j;
            if (AMODE == 1) {
                const int k = idx >> 5, mq = idx & 31;
                ra[j] = *(const float4*)&Ab[(size_t)(kt + k) * lda + m0 + mq * 4];
            } else {
                const int m = idx >> 3, f4 = idx & 7;
                const int kk = kt + f4 * 4;
                const float* src;
                if (AMODE == 2)
                    src = (kk < CD) ? &Ab[(size_t)(m0 + m) * CD + kk]
                                    : &A2[(size_t)(m0 + m) * CD + (kk - CD)];
                else
                    src = &Ab[(size_t)(m0 + m) * lda + kk];
                ra[j] = *(const float4*)src;
            }
        }
#pragma unroll
        for (int j = 0; j < 4; j++) {
            const int idx = tid + 256 * j;
            const int kr = idx >> 5, nq = idx & 31;
            rb[j] = *(const float4*)&Bb[(size_t)(kt + kr) * ldb + n0 + nq * 4];
        }
    };

    auto stsTiles = [&](int buf) {
        uint32_t* Aw = sm + buf * BUFWORDS;
        uint32_t* Bw = Aw + AWORDS;
#pragma unroll
        for (int j = 0; j < 4; j++) {
            const int idx = tid + 256 * j;
            float v[4] = {ra[j].x, ra[j].y, ra[j].z, ra[j].w};
            if (AMODE == 1) {
                const int k = idx >> 5, mq = idx & 31;
#pragma unroll
                for (int e = 0; e < 4; e++) {
                    const int m = mq * 4 + e;
                    Aw[m * 32 + (k ^ ((m & 7) << 2))] = f2tf(v[e]);
                }
            } else {
                const int m = idx >> 3, f4 = idx & 7;
                const int base = m * 32 + ((f4 * 4) ^ ((m & 7) << 2));
                uint4 w;
                w.x = f2tf(v[0]); w.y = f2tf(v[1]);
                w.z = f2tf(v[2]); w.w = f2tf(v[3]);
                *(uint4*)&Aw[base] = w;
            }
        }
#pragma unroll
        for (int j = 0; j < 4; j++) {
            const int idx = tid + 256 * j;
            const int kr = idx >> 5, nq = idx & 31;
            const int base = kr * 128 + ((nq * 4) ^ ((kr & 3) << 3));
            uint4 w;
            w.x = f2tf(rb[j].x); w.y = f2tf(rb[j].y);
            w.z = f2tf(rb[j].z); w.w = f2tf(rb[j].w);
            *(uint4*)&Bw[base] = w;
        }
    };

    float acc[4][4][4];
#pragma unroll
    for (int i = 0; i < 4; i++)
#pragma unroll
        for (int j = 0; j < 4; j++)
#pragma unroll
            for (int e = 0; e < 4; e++) acc[i][j][e] = 0.0f;

    // prologue
    loadTiles(k0);
    stsTiles(0);
    __syncthreads();

    for (int it = 0; it < T; ++it) {
        const int cur = it & 1;
        if (it + 1 < T) loadTiles(k0 + (it + 1) * BK);

        const uint32_t* Aw = sm + cur * BUFWORDS;
        const uint32_t* Bw = Aw + AWORDS;
#pragma unroll
        for (int ks = 0; ks < 4; ks++) {
            uint32_t bf[4][2];
            const int kb0 = (ks * 8 + tig) * 128;
#pragma unroll
            for (int jt = 0; jt < 4; jt++) {
                const int nx = ((wn * 4 + jt) * 8 + gid) ^ (tig << 3);
                bf[jt][0] = Bw[kb0 + nx];
                bf[jt][1] = Bw[kb0 + 512 + nx];
            }
            const int c = ks * 8 + tig;
#pragma unroll
            for (int i = 0; i < 4; i++) {
                const int r = (wm * 4 + i) * 16 + gid;
                const int w0 = r * 32 + (c ^ (gid << 2));
                uint32_t af[4];
                af[0] = Aw[w0];
                af[1] = Aw[w0 + 256];
                af[2] = Aw[w0 ^ 4];
                af[3] = Aw[(w0 + 256) ^ 4];
#pragma unroll
                for (int jt = 0; jt < 4; jt++)
                    mma_tf32(acc[i][jt], af, bf[jt]);
            }
        }

        if (it + 1 < T) stsTiles((it + 1) & 1);
        __syncthreads();
    }

    // ---- epilogue: reg -> gmem, fused bias/GELU ----
#pragma unroll
    for (int i = 0; i < 4; i++) {
        const int rbase = m0 + wm * 64 + i * 16 + gid;
#pragma unroll
        for (int j = 0; j < 4; j++) {
            const int cn = n0 + wn * 32 + j * 8 + tig * 2;
            float bia0 = 0.f, bia1 = 0.f;
            if (EPI >= 1) { bia0 = bias[cn]; bia1 = bias[cn + 1]; }
#pragma unroll
            for (int h = 0; h < 2; h++) {
                const int row = rbase + h * 8;
                float v0 = acc[i][j][2 * h + 0] + bia0;
                float v1 = acc[i][j][2 * h + 1] + bia1;
                if (EPI == 2) {
                    v0 = 0.5f * v0 * (1.0f + erff(v0 * 0.70710678118654752f));
                    v1 = 0.5f * v1 * (1.0f + erff(v1 * 0.70710678118654752f));
                }
                float2 out; out.x = v0; out.y = v1;
                *(float2*)&Cb[(size_t)row * ldc + cn] = out;
            }
        }
    }
}

// ---------------- column softmax of K over token dim ----------------
__global__ void softmax_cols(float* __restrict__ Kp, float* __restrict__ colsum)
{
    const int bc = blockIdx.x;
    const int b  = bc / (CD / 32);
    const int cg = bc - b * (CD / 32);
    const int tx = threadIdx.x, ty = threadIdx.y;
    const int c  = cg * 32 + tx;
    float* Kb = Kp + (size_t)b * LD * CD + c;

    __shared__ float red[32][33];

    float m = -INFINITY;
    for (int l = ty; l < LD; l += 32)
        m = fmaxf(m, Kb[(size_t)l * CD]);
    red[ty][tx] = m;
    __syncthreads();
    for (int sft = 16; sft > 0; sft >>= 1) {
        if (ty < sft) red[ty][tx] = fmaxf(red[ty][tx], red[ty + sft][tx]);
        __syncthreads();
    }
    m = red[0][tx];
    __syncthreads();

    float sum = 0.0f;
    for (int l = ty; l < LD; l += 32) {
        float e = expf(Kb[(size_t)l * CD] - m);
        Kb[(size_t)l * CD] = e;
        sum += e;
    }
    red[ty][tx] = sum;
    __syncthreads();
    for (int sft = 16; sft > 0; sft >>= 1) {
        if (ty < sft) red[ty][tx] += red[ty + sft][tx];
        __syncthreads();
    }
    if (ty == 0) colsum[b * CD + c] = red[0][tx];
}

// ---------------- reduce split-K context partials; fold 1/colsum ----------
__global__ void ctx_reduce(const float* __restrict__ part,
                           const float* __restrict__ colsum,
                           float* __restrict__ ctx)
{
    const int idx = blockIdx.x * 256 + threadIdx.x;
    const int b  = idx / (CD * CD);
    const int de = idx - b * (CD * CD);
    const int e  = de & (CD - 1);
    float s = 0.0f;
#pragma unroll
    for (int p = 0; p < NS; p++)
        s += part[((size_t)b * NS + p) * CD * CD + de];
    ctx[idx] = s / colsum[b * CD + e];
}

// ---------------- row LayerNorm over C=256 ----------------
__global__ void ln_rows(const float* __restrict__ X, const float* __restrict__ src,
                        const float* __restrict__ gamma, const float* __restrict__ beta,
                        float* __restrict__ out, int addRes)
{
    const int row  = blockIdx.x * 8 + threadIdx.y;
    const int lane = threadIdx.x;
    const float* x = X + (size_t)row * CD;

    float v[8];
#pragma unroll
    for (int i = 0; i < 8; i++) v[i] = x[lane + i * 32];

    float s = 0.0f;
#pragma unroll
    for (int i = 0; i < 8; i++) s += v[i];
#pragma unroll
    for (int o = 16; o > 0; o >>= 1) s += __shfl_xor_sync(0xffffffffu, s, o);
    const float mu = s * (1.0f / CD);

    float q = 0.0f;
#pragma unroll
    for (int i = 0; i < 8; i++) { float d = v[i] - mu; q += d * d; }
#pragma unroll
    for (int o = 16; o > 0; o >>= 1) q += __shfl_xor_sync(0xffffffffu, q, o);
    const float rstd = rsqrtf(q * (1.0f / CD) + EPSL);

#pragma unroll
    for (int i = 0; i < 8; i++) {
        const int c = lane + i * 32;
        float y = (v[i] - mu) * rstd * gamma[c] + beta[c];
        if (addRes) y += src[(size_t)row * CD + c];
        out[(size_t)row * CD + c] = y;
    }
}

// ---------------- launcher ----------------
extern "C" void kernel_launch(void* const* d_in, const int* in_sizes, int n_in,
                              void* d_out, int out_size)
{
    const float* source = (const float*)d_in[0];
    const float* target = (const float*)d_in[1];
    const float* Wq     = (const float*)d_in[2];
    const float* Wk     = (const float*)d_in[3];
    const float* Wv     = (const float*)d_in[4];
    const float* Wl     = (const float*)d_in[5];
    const float* gamma1 = (const float*)d_in[6];
    const float* beta1  = (const float*)d_in[7];
    const float* W1     = (const float*)d_in[8];
    const float* b1     = (const float*)d_in[9];
    const float* W2     = (const float*)d_in[10];
    const float* b2     = (const float*)d_in[11];
    const float* gamma2 = (const float*)d_in[12];
    const float* beta2  = (const float*)d_in[13];

    float *Q, *Kb, *V, *colsum, *ctxpart, *ctx, *Mm, *attn, *hidden, *tmp2;
    cudaGetSymbolAddress((void**)&Q,       g_Q);
    cudaGetSymbolAddress((void**)&Kb,      g_K);
    cudaGetSymbolAddress((void**)&V,       g_V);
    cudaGetSymbolAddress((void**)&colsum,  g_colsum);
    cudaGetSymbolAddress((void**)&ctxpart, g_ctxpart);
    cudaGetSymbolAddress((void**)&ctx,     g_ctx);
    cudaGetSymbolAddress((void**)&Mm,      g_Mm);
    cudaGetSymbolAddress((void**)&attn,    g_attn);
    cudaGetSymbolAddress((void**)&hidden,  g_hidden);
    cudaGetSymbolAddress((void**)&tmp2,    g_tmp2);

    cudaFuncSetAttribute(tgemm<0, 0>, cudaFuncAttributeMaxDynamicSharedMemorySize, SMEM_TOTAL);
    cudaFuncSetAttribute(tgemm<1, 0>, cudaFuncAttributeMaxDynamicSharedMemorySize, SMEM_TOTAL);
    cudaFuncSetAttribute(tgemm<2, 2>, cudaFuncAttributeMaxDynamicSharedMemorySize, SMEM_TOTAL);
    cudaFuncSetAttribute(tgemm<0, 1>, cudaFuncAttributeMaxDynamicSharedMemorySize, SMEM_TOTAL);

    const long long LC = (long long)LD * CD;
    const long long CC = (long long)CD * CD;

    // 1-3) Q/K/V projections (M=32768, N=256, K=256)
    tgemm<0, 0><<<dim3(2, 256, 1), 256, SMEM_TOTAL>>>(source, nullptr, Wq, nullptr, Q,
                                                      CD, 1, CD, CD, CD, 0, 0, 0);
    tgemm<0, 0><<<dim3(2, 256, 1), 256, SMEM_TOTAL>>>(target, nullptr, Wk, nullptr, Kb,
                                                      CD, 1, CD, CD, CD, 0, 0, 0);
    tgemm<0, 0><<<dim3(2, 256, 1), 256, SMEM_TOTAL>>>(target, nullptr, Wv, nullptr, V,
                                                      CD, 1, CD, CD, CD, 0, 0, 0);

    // 4) column softmax over tokens
    softmax_cols<<<BD * (CD / 32), dim3(32, 32)>>>(Kb, colsum);

    // 5) context partials: ctxpart[b][s] = Q^T(chunk) @ expK
    tgemm<1, 0><<<dim3(2, 2, BD * NS), 256, SMEM_TOTAL>>>(Q, nullptr, Kb, nullptr, ctxpart,
                                                          LD, NS, CD, CD, CD, LC, LC, CC);

    // 6) reduce + 1/colsum
    ctx_reduce<<<BD * CD * CD / 256, 256>>>(ctxpart, colsum, ctx);

    // 7) Mm = ctx^T @ Wl
    tgemm<1, 0><<<dim3(2, 2, BD), 256, SMEM_TOTAL>>>(ctx, nullptr, Wl, nullptr, Mm,
                                                     CD, 1, CD, CD, CD, CC, 0, CC);

    // 8) attn = V @ Mm
    tgemm<0, 0><<<dim3(2, 64, BD), 256, SMEM_TOTAL>>>(V, nullptr, Mm, nullptr, attn,
                                                      CD, 1, CD, CD, CD, LC, CC, LC);

    // 9) message = LN(attn)
    ln_rows<<<BD * LD / 8, dim3(32, 8)>>>(attn, nullptr, gamma1, beta1, attn, 0);

    // 10) hidden = gelu([source, message] @ W1 + b1)
    tgemm<2, 2><<<dim3(16, 256, 1), 256, SMEM_TOTAL>>>(source, attn, W1, b1, hidden,
                                                       2 * CD, 1, CD, HID, HID, 0, 0, 0);

    // 11) tmp2 = hidden @ W2 + b2
    tgemm<0, 1><<<dim3(2, 256, 1), 256, SMEM_TOTAL>>>(hidden, nullptr, W2, b2, tmp2,
                                                      HID, 1, HID, CD, CD, 0, 0, 0);

    // 12) out = source + LN(tmp2)
    ln_rows<<<BD * LD / 8, dim3(32, 8)>>>(tmp2, source, gamma2, beta2,
                                          (float*)d_out, 1);
}

// round 5
// speedup vs baseline: 3.8756x; 1.3852x over previous
#include <cuda_runtime.h>
#include <math.h>
#include <stdint.h>

// Problem constants
#define BD   4
#define LD   8192
#define CD   256
#define HID  2048
#define NS   16
#define EPSL 1e-5f

// ---------------- scratch (__device__ globals; no allocations) ----------------
__device__ float g_Q[BD * LD * CD];
__device__ float g_K[BD * LD * CD];
__device__ float g_V[BD * LD * CD];
__device__ float g_colsum[BD * CD];
__device__ float g_ctxpart[BD * NS * CD * CD];
__device__ float g_ctx[BD * CD * CD];
__device__ float g_Mm[BD * CD * CD];
__device__ float g_attn[BD * LD * CD];
__device__ float g_hidden[BD * LD * HID];
__device__ float g_tmp2[BD * LD * CD];
__device__ float g_srcR[BD * LD * CD];
__device__ float g_tgtR[BD * LD * CD];
__device__ float g_WqR[CD * CD];
__device__ float g_WkR[CD * CD];
__device__ float g_WvR[CD * CD];
__device__ float g_WlR[CD * CD];
__device__ float g_W1R[2 * CD * HID];
__device__ float g_W2R[HID * CD];

// ---------------- helpers ----------------
__device__ __forceinline__ uint32_t f2tf(float f) {
    uint32_t r; asm("cvt.rna.tf32.f32 %0, %1;" : "=r"(r) : "f"(f)); return r;
}
__device__ __forceinline__ float roundtf(float f) {
    return __uint_as_float(f2tf(f));
}
__device__ __forceinline__ void mma_tf32(float* c, const uint32_t* a, const uint32_t* b) {
    asm volatile(
        "mma.sync.aligned.m16n8k8.row.col.f32.tf32.tf32.f32 "
        "{%0,%1,%2,%3}, {%4,%5,%6,%7}, {%8,%9}, {%0,%1,%2,%3};"
        : "+f"(c[0]), "+f"(c[1]), "+f"(c[2]), "+f"(c[3])
        : "r"(a[0]), "r"(a[1]), "r"(a[2]), "r"(a[3]), "r"(b[0]), "r"(b[1]));
}
__device__ __forceinline__ void cpasync16(uint32_t dst, const void* src) {
    asm volatile("cp.async.cg.shared.global [%0], [%1], 16;" :: "r"(dst), "l"(src));
}
__device__ __forceinline__ void cp_commit() {
    asm volatile("cp.async.commit_group;" ::: "memory");
}

// ---------------- GEMM tiling ----------------
// CTA tile 128x128x32; 8 warps (2 m x 4 n), warp tile 64x32.
// SMEM word layouts (bank-conflict-free, 16B-chunk preserving):
//   A: word(m,k) = m*32 + (k ^ ((m&7)<<2))     (128 rows x 32 kwords)
//   B: word(k,n) = k*128 + (n ^ ((k&3)<<3))    (32 krows x 128 nwords)
#define BM 128
#define BN 128
#define BK 32
#define AWORDS 4096
#define BUFWORDS 8192
#define SMEM_ASYNC (3 * BUFWORDS * 4)    // 98304 (3-stage)
#define SMEM_T     (2 * BUFWORDS * 4)    // 65536 (2-stage, register path)

// ============ cp.async pipelined GEMM (A row-major / concat). All operands
// pre-rounded to tf32 in gmem. EPI: 0 store; 1 +bias; 2 +bias+GELU. RND: round C.
template <int AMODE, int EPI, int RND>
__global__ void __launch_bounds__(256, 2)
tgemm_async(const float* __restrict__ A, const float* __restrict__ A2,
            const float* __restrict__ Bm, const float* __restrict__ bias,
            float* __restrict__ Cmat,
            int Kd, int lda, int ldb, int ldc,
            long long sA, long long sB, long long sC)
{
    extern __shared__ uint32_t sm[];
    const uint32_t sbase = (uint32_t)__cvta_generic_to_shared(sm);
    const int tid = threadIdx.x;
    const int wid = tid >> 5, lane = tid & 31;
    const int wm = wid >> 2, wn = wid & 3;
    const int gid = lane >> 2, tig = lane & 3;

    const int b = blockIdx.z;
    const float* Ab = A + (long long)b * sA;
    const float* Bb = Bm + (long long)b * sB;
    float* Cb = Cmat + (long long)b * sC;
    const int T = Kd / BK;
    const int m0 = blockIdx.y * BM;
    const int n0 = blockIdx.x * BN;

    auto issue = [&](int it) {
        const int buf = it % 3;
        const uint32_t Abase = sbase + (uint32_t)buf * (BUFWORDS * 4);
        const uint32_t Bbase = Abase + AWORDS * 4;
        const int kt = it * BK;
#pragma unroll
        for (int j = 0; j < 4; j++) {
            const int idx = tid + 256 * j;
            const int m = idx >> 3, f4 = idx & 7;
            const int kk = kt + f4 * 4;
            const float* src;
            if (AMODE == 2)
                src = (kk < CD) ? &Ab[(size_t)(m0 + m) * CD + kk]
                                : &A2[(size_t)(m0 + m) * CD + (kk - CD)];
            else
                src = &Ab[(size_t)(m0 + m) * lda + kk];
            const uint32_t dw = (uint32_t)(m * 32 + ((f4 * 4) ^ ((m & 7) << 2)));
            cpasync16(Abase + dw * 4, src);
        }
#pragma unroll
        for (int j = 0; j < 4; j++) {
            const int idx = tid + 256 * j;
            const int kr = idx >> 5, nq = idx & 31;
            const float* src = &Bb[(size_t)(kt + kr) * ldb + n0 + nq * 4];
            const uint32_t dw = (uint32_t)(kr * 128 + ((nq * 4) ^ ((kr & 3) << 3)));
            cpasync16(Bbase + dw * 4, src);
        }
        cp_commit();
    };

    float acc[4][4][4];
#pragma unroll
    for (int i = 0; i < 4; i++)
#pragma unroll
        for (int j = 0; j < 4; j++)
#pragma unroll
            for (int e = 0; e < 4; e++) acc[i][j][e] = 0.0f;

    issue(0);
    issue(1);

    for (int it = 0; it < T; ++it) {
        if (it + 1 < T) asm volatile("cp.async.wait_group 1;" ::: "memory");
        else            asm volatile("cp.async.wait_group 0;" ::: "memory");
        __syncthreads();
        if (it + 2 < T) issue(it + 2);

        const uint32_t* Aw = sm + (it % 3) * BUFWORDS;
        const uint32_t* Bw = Aw + AWORDS;
#pragma unroll
        for (int ks = 0; ks < 4; ks++) {
            uint32_t bf[4][2];
            const int kb0 = (ks * 8 + tig) * 128;
#pragma unroll
            for (int jt = 0; jt < 4; jt++) {
                const int nx = ((wn * 4 + jt) * 8 + gid) ^ (tig << 3);
                bf[jt][0] = Bw[kb0 + nx];
                bf[jt][1] = Bw[kb0 + 512 + nx];
            }
            const int c = ks * 8 + tig;
#pragma unroll
            for (int i = 0; i < 4; i++) {
                const int r = (wm * 4 + i) * 16 + gid;
                const int w0 = r * 32 + (c ^ (gid << 2));
                uint32_t af[4];
                af[0] = Aw[w0];
                af[1] = Aw[w0 + 256];
                af[2] = Aw[w0 ^ 4];
                af[3] = Aw[(w0 + 256) ^ 4];
#pragma unroll
                for (int jt = 0; jt < 4; jt++)
                    mma_tf32(acc[i][jt], af, bf[jt]);
            }
        }
        __syncthreads();
    }

    // ---- epilogue: reg -> gmem, fused bias/GELU (+optional tf32 rounding) ----
#pragma unroll
    for (int i = 0; i < 4; i++) {
        const int rbase = m0 + wm * 64 + i * 16 + gid;
#pragma unroll
        for (int j = 0; j < 4; j++) {
            const int cn = n0 + wn * 32 + j * 8 + tig * 2;
            float bia0 = 0.f, bia1 = 0.f;
            if (EPI >= 1) { bia0 = bias[cn]; bia1 = bias[cn + 1]; }
#pragma unroll
            for (int h = 0; h < 2; h++) {
                const int row = rbase + h * 8;
                float v0 = acc[i][j][2 * h + 0] + bia0;
                float v1 = acc[i][j][2 * h + 1] + bia1;
                if (EPI == 2) {
                    v0 = 0.5f * v0 * (1.0f + erff(v0 * 0.70710678118654752f));
                    v1 = 0.5f * v1 * (1.0f + erff(v1 * 0.70710678118654752f));
                }
                if (RND) { v0 = roundtf(v0); v1 = roundtf(v1); }
                float2 out; out.x = v0; out.y = v1;
                *(float2*)&Cb[(size_t)row * ldc + cn] = out;
            }
        }
    }
}

// ============ transposed-A GEMM (register path; operands pre-rounded) ============
template <int RND>
__global__ void __launch_bounds__(256)
tgemm_t(const float* __restrict__ A, const float* __restrict__ Bm,
        float* __restrict__ Cmat,
        int Kd, int nsplit, int lda, int ldb, int ldc,
        long long sA, long long sB, long long sC)
{
    extern __shared__ uint32_t sm[];
    const int tid = threadIdx.x;
    const int wid = tid >> 5, lane = tid & 31;
    const int wm = wid >> 2, wn = wid & 3;
    const int gid = lane >> 2, tig = lane & 3;

    const int z = blockIdx.z;
    const int b = z / nsplit;
    const int s = z - b * nsplit;
    const float* Ab = A + (long long)b * sA;
    const float* Bb = Bm + (long long)b * sB;
    float* Cb = Cmat + (long long)z * sC;
    const int kChunk = Kd / nsplit;
    const int k0 = s * kChunk;
    const int T = kChunk / BK;
    const int m0 = blockIdx.y * BM;
    const int n0 = blockIdx.x * BN;

    float4 ra[4], rb[4];

    auto loadTiles = [&](int kt) {
#pragma unroll
        for (int j = 0; j < 4; j++) {
            const int idx = tid + 256 * j;
            const int k = idx >> 5, mq = idx & 31;
            ra[j] = *(const float4*)&Ab[(size_t)(kt + k) * lda + m0 + mq * 4];
        }
#pragma unroll
        for (int j = 0; j < 4; j++) {
            const int idx = tid + 256 * j;
            const int kr = idx >> 5, nq = idx & 31;
            rb[j] = *(const float4*)&Bb[(size_t)(kt + kr) * ldb + n0 + nq * 4];
        }
    };

    auto stsTiles = [&](int buf) {
        uint32_t* Aw = sm + buf * BUFWORDS;
        uint32_t* Bw = Aw + AWORDS;
#pragma unroll
        for (int j = 0; j < 4; j++) {
            const int idx = tid + 256 * j;
            const int k = idx >> 5, mq = idx & 31;
            float v[4] = {ra[j].x, ra[j].y, ra[j].z, ra[j].w};
#pragma unroll
            for (int e = 0; e < 4; e++) {
                const int m = mq * 4 + e;
                Aw[m * 32 + (k ^ ((m & 7) << 2))] = __float_as_uint(v[e]);
            }
        }
#pragma unroll
        for (int j = 0; j < 4; j++) {
            const int idx = tid + 256 * j;
            const int kr = idx >> 5, nq = idx & 31;
            const int base = kr * 128 + ((nq * 4) ^ ((kr & 3) << 3));
            uint4 w;
            w.x = __float_as_uint(rb[j].x); w.y = __float_as_uint(rb[j].y);
            w.z = __float_as_uint(rb[j].z); w.w = __float_as_uint(rb[j].w);
            *(uint4*)&Bw[base] = w;
        }
    };

    float acc[4][4][4];
#pragma unroll
    for (int i = 0; i < 4; i++)
#pragma unroll
        for (int j = 0; j < 4; j++)
#pragma unroll
            for (int e = 0; e < 4; e++) acc[i][j][e] = 0.0f;

    loadTiles(k0);
    stsTiles(0);
    __syncthreads();

    for (int it = 0; it < T; ++it) {
        const int cur = it & 1;
        if (it + 1 < T) loadTiles(k0 + (it + 1) * BK);

        const uint32_t* Aw = sm + cur * BUFWORDS;
        const uint32_t* Bw = Aw + AWORDS;
#pragma unroll
        for (int ks = 0; ks < 4; ks++) {
            uint32_t bf[4][2];
            const int kb0 = (ks * 8 + tig) * 128;
#pragma unroll
            for (int jt = 0; jt < 4; jt++) {
                const int nx = ((wn * 4 + jt) * 8 + gid) ^ (tig << 3);
                bf[jt][0] = Bw[kb0 + nx];
                bf[jt][1] = Bw[kb0 + 512 + nx];
            }
            const int c = ks * 8 + tig;
#pragma unroll
            for (int i = 0; i < 4; i++) {
                const int r = (wm * 4 + i) * 16 + gid;
                const int w0 = r * 32 + (c ^ (gid << 2));
                uint32_t af[4];
                af[0] = Aw[w0];
                af[1] = Aw[w0 + 256];
                af[2] = Aw[w0 ^ 4];
                af[3] = Aw[(w0 + 256) ^ 4];
#pragma unroll
                for (int jt = 0; jt < 4; jt++)
                    mma_tf32(acc[i][jt], af, bf[jt]);
            }
        }

        if (it + 1 < T) stsTiles((it + 1) & 1);
        __syncthreads();
    }

#pragma unroll
    for (int i = 0; i < 4; i++) {
        const int rbase = m0 + wm * 64 + i * 16 + gid;
#pragma unroll
        for (int j = 0; j < 4; j++) {
            const int cn = n0 + wn * 32 + j * 8 + tig * 2;
#pragma unroll
            for (int h = 0; h < 2; h++) {
                const int row = rbase + h * 8;
                float v0 = acc[i][j][2 * h + 0];
                float v1 = acc[i][j][2 * h + 1];
                if (RND) { v0 = roundtf(v0); v1 = roundtf(v1); }
                float2 out; out.x = v0; out.y = v1;
                *(float2*)&Cb[(size_t)row * ldc + cn] = out;
            }
        }
    }
}

// ---------------- tf32 rounding copy (float4) ----------------
__global__ void round_tf(const float4* __restrict__ in, float4* __restrict__ out, int n4)
{
    const int i = blockIdx.x * 256 + threadIdx.x;
    if (i < n4) {
        float4 v = in[i];
        v.x = roundtf(v.x); v.y = roundtf(v.y);
        v.z = roundtf(v.z); v.w = roundtf(v.w);
        out[i] = v;
    }
}

// ---------------- column softmax of K over token dim (stores rounded exp) ------
__global__ void softmax_cols(float* __restrict__ Kp, float* __restrict__ colsum)
{
    const int bc = blockIdx.x;
    const int b  = bc / (CD / 32);
    const int cg = bc - b * (CD / 32);
    const int tx = threadIdx.x, ty = threadIdx.y;
    const int c  = cg * 32 + tx;
    float* Kb = Kp + (size_t)b * LD * CD + c;

    __shared__ float red[32][33];

    float m = -INFINITY;
    for (int l = ty; l < LD; l += 32)
        m = fmaxf(m, Kb[(size_t)l * CD]);
    red[ty][tx] = m;
    __syncthreads();
    for (int sft = 16; sft > 0; sft >>= 1) {
        if (ty < sft) red[ty][tx] = fmaxf(red[ty][tx], red[ty + sft][tx]);
        __syncthreads();
    }
    m = red[0][tx];
    __syncthreads();

    float sum = 0.0f;
    for (int l = ty; l < LD; l += 32) {
        float e = roundtf(expf(Kb[(size_t)l * CD] - m));
        Kb[(size_t)l * CD] = e;
        sum += e;
    }
    red[ty][tx] = sum;
    __syncthreads();
    for (int sft = 16; sft > 0; sft >>= 1) {
        if (ty < sft) red[ty][tx] += red[ty + sft][tx];
        __syncthreads();
    }
    if (ty == 0) colsum[b * CD + c] = red[0][tx];
}

// ---------------- reduce split-K context partials; fold 1/colsum, round -------
__global__ void ctx_reduce(const float* __restrict__ part,
                           const float* __restrict__ colsum,
                           float* __restrict__ ctx)
{
    const int idx = blockIdx.x * 256 + threadIdx.x;
    const int b  = idx / (CD * CD);
    const int de = idx - b * (CD * CD);
    const int e  = de & (CD - 1);
    float s = 0.0f;
#pragma unroll
    for (int p = 0; p < NS; p++)
        s += part[((size_t)b * NS + p) * CD * CD + de];
    ctx[idx] = roundtf(s / colsum[b * CD + e]);
}

// ---------------- row LayerNorm over C=256 ----------------
__global__ void ln_rows(const float* __restrict__ X, const float* __restrict__ src,
                        const float* __restrict__ gamma, const float* __restrict__ beta,
                        float* __restrict__ out, int addRes, int rnd)
{
    const int row  = blockIdx.x * 8 + threadIdx.y;
    const int lane = threadIdx.x;
    const float* x = X + (size_t)row * CD;

    float v[8];
#pragma unroll
    for (int i = 0; i < 8; i++) v[i] = x[lane + i * 32];

    float s = 0.0f;
#pragma unroll
    for (int i = 0; i < 8; i++) s += v[i];
#pragma unroll
    for (int o = 16; o > 0; o >>= 1) s += __shfl_xor_sync(0xffffffffu, s, o);
    const float mu = s * (1.0f / CD);

    float q = 0.0f;
#pragma unroll
    for (int i = 0; i < 8; i++) { float d = v[i] - mu; q += d * d; }
#pragma unroll
    for (int o = 16; o > 0; o >>= 1) q += __shfl_xor_sync(0xffffffffu, q, o);
    const float rstd = rsqrtf(q * (1.0f / CD) + EPSL);

#pragma unroll
    for (int i = 0; i < 8; i++) {
        const int c = lane + i * 32;
        float y = (v[i] - mu) * rstd * gamma[c] + beta[c];
        if (addRes) y += src[(size_t)row * CD + c];
        if (rnd) y = roundtf(y);
        out[(size_t)row * CD + c] = y;
    }
}

// ---------------- launcher ----------------
extern "C" void kernel_launch(void* const* d_in, const int* in_sizes, int n_in,
                              void* d_out, int out_size)
{
    const float* source = (const float*)d_in[0];
    const float* target = (const float*)d_in[1];
    const float* Wq     = (const float*)d_in[2];
    const float* Wk     = (const float*)d_in[3];
    const float* Wv     = (const float*)d_in[4];
    const float* Wl     = (const float*)d_in[5];
    const float* gamma1 = (const float*)d_in[6];
    const float* beta1  = (const float*)d_in[7];
    const float* W1     = (const float*)d_in[8];
    const float* b1     = (const float*)d_in[9];
    const float* W2     = (const float*)d_in[10];
    const float* b2     = (const float*)d_in[11];
    const float* gamma2 = (const float*)d_in[12];
    const float* beta2  = (const float*)d_in[13];

    float *Q, *Kb, *V, *colsum, *ctxpart, *ctx, *Mm, *attn, *hidden, *tmp2;
    float *srcR, *tgtR, *WqR, *WkR, *WvR, *WlR, *W1R, *W2R;
    cudaGetSymbolAddress((void**)&Q,       g_Q);
    cudaGetSymbolAddress((void**)&Kb,      g_K);
    cudaGetSymbolAddress((void**)&V,       g_V);
    cudaGetSymbolAddress((void**)&colsum,  g_colsum);
    cudaGetSymbolAddress((void**)&ctxpart, g_ctxpart);
    cudaGetSymbolAddress((void**)&ctx,     g_ctx);
    cudaGetSymbolAddress((void**)&Mm,      g_Mm);
    cudaGetSymbolAddress((void**)&attn,    g_attn);
    cudaGetSymbolAddress((void**)&hidden,  g_hidden);
    cudaGetSymbolAddress((void**)&tmp2,    g_tmp2);
    cudaGetSymbolAddress((void**)&srcR,    g_srcR);
    cudaGetSymbolAddress((void**)&tgtR,    g_tgtR);
    cudaGetSymbolAddress((void**)&WqR,     g_WqR);
    cudaGetSymbolAddress((void**)&WkR,     g_WkR);
    cudaGetSymbolAddress((void**)&WvR,     g_WvR);
    cudaGetSymbolAddress((void**)&WlR,     g_WlR);
    cudaGetSymbolAddress((void**)&W1R,     g_W1R);
    cudaGetSymbolAddress((void**)&W2R,     g_W2R);

    cudaFuncSetAttribute(tgemm_async<0, 0, 1>, cudaFuncAttributeMaxDynamicSharedMemorySize, SMEM_ASYNC);
    cudaFuncSetAttribute(tgemm_async<0, 0, 0>, cudaFuncAttributeMaxDynamicSharedMemorySize, SMEM_ASYNC);
    cudaFuncSetAttribute(tgemm_async<2, 2, 1>, cudaFuncAttributeMaxDynamicSharedMemorySize, SMEM_ASYNC);
    cudaFuncSetAttribute(tgemm_async<0, 1, 0>, cudaFuncAttributeMaxDynamicSharedMemorySize, SMEM_ASYNC);
    cudaFuncSetAttribute(tgemm_t<0>,           cudaFuncAttributeMaxDynamicSharedMemorySize, SMEM_T);
    cudaFuncSetAttribute(tgemm_t<1>,           cudaFuncAttributeMaxDynamicSharedMemorySize, SMEM_T);

    const long long LC = (long long)LD * CD;
    const long long CC = (long long)CD * CD;
    const int NLC = BD * LD * CD;

    // 0) tf32-round inputs and weights
    round_tf<<<(NLC / 4 + 255) / 256, 256>>>((const float4*)source, (float4*)srcR, NLC / 4);
    round_tf<<<(NLC / 4 + 255) / 256, 256>>>((const float4*)target, (float4*)tgtR, NLC / 4);
    round_tf<<<(CD * CD / 4 + 255) / 256, 256>>>((const float4*)Wq, (float4*)WqR, CD * CD / 4);
    round_tf<<<(CD * CD / 4 + 255) / 256, 256>>>((const float4*)Wk, (float4*)WkR, CD * CD / 4);
    round_tf<<<(CD * CD / 4 + 255) / 256, 256>>>((const float4*)Wv, (float4*)WvR, CD * CD / 4);
    round_tf<<<(CD * CD / 4 + 255) / 256, 256>>>((const float4*)Wl, (float4*)WlR, CD * CD / 4);
    round_tf<<<(2 * CD * HID / 4 + 255) / 256, 256>>>((const float4*)W1, (float4*)W1R, 2 * CD * HID / 4);
    round_tf<<<(HID * CD / 4 + 255) / 256, 256>>>((const float4*)W2, (float4*)W2R, HID * CD / 4);

    // 1-3) Q/K/V projections (M=32768, N=256, K=256)
    tgemm_async<0, 0, 1><<<dim3(2, 256, 1), 256, SMEM_ASYNC>>>(srcR, nullptr, WqR, nullptr, Q,
                                                               CD, CD, CD, CD, 0, 0, 0);
    tgemm_async<0, 0, 0><<<dim3(2, 256, 1), 256, SMEM_ASYNC>>>(tgtR, nullptr, WkR, nullptr, Kb,
                                                               CD, CD, CD, CD, 0, 0, 0);
    tgemm_async<0, 0, 1><<<dim3(2, 256, 1), 256, SMEM_ASYNC>>>(tgtR, nullptr, WvR, nullptr, V,
                                                               CD, CD, CD, CD, 0, 0, 0);

    // 4) column softmax over tokens (stores rounded exp)
    softmax_cols<<<BD * (CD / 32), dim3(32, 32)>>>(Kb, colsum);

    // 5) context partials: ctxpart[b][s] = Q^T(chunk) @ expK
    tgemm_t<0><<<dim3(2, 2, BD * NS), 256, SMEM_T>>>(Q, Kb, ctxpart,
                                                     LD, NS, CD, CD, CD, LC, LC, CC);

    // 6) reduce + 1/colsum (rounds)
    ctx_reduce<<<BD * CD * CD / 256, 256>>>(ctxpart, colsum, ctx);

    // 7) Mm = ctx^T @ Wl (rounds)
    tgemm_t<1><<<dim3(2, 2, BD), 256, SMEM_T>>>(ctx, WlR, Mm,
                                                CD, 1, CD, CD, CD, CC, 0, CC);

    // 8) attn = V @ Mm
    tgemm_async<0, 0, 0><<<dim3(2, 64, BD), 256, SMEM_ASYNC>>>(V, nullptr, Mm, nullptr, attn,
                                                               CD, CD, CD, CD, LC, CC, LC);

    // 9) message = LN(attn), rounded
    ln_rows<<<BD * LD / 8, dim3(32, 8)>>>(attn, nullptr, gamma1, beta1, attn, 0, 1);

    // 10) hidden = gelu([srcR, message] @ W1 + b1), rounded
    tgemm_async<2, 2, 1><<<dim3(16, 256, 1), 256, SMEM_ASYNC>>>(srcR, attn, W1R, b1, hidden,
                                                                2 * CD, CD, HID, HID, 0, 0, 0);

    // 11) tmp2 = hidden @ W2 + b2
    tgemm_async<0, 1, 0><<<dim3(2, 256, 1), 256, SMEM_ASYNC>>>(hidden, nullptr, W2R, b2, tmp2,
                                                               HID, HID, CD, CD, 0, 0, 0);

    // 12) out = source + LN(tmp2)  (original source for residual)
    ln_rows<<<BD * LD / 8, dim3(32, 8)>>>(tmp2, source, gamma2, beta2,
                                          (float*)d_out, 1, 0);
}

// round 7
// speedup vs baseline: 4.1297x; 1.0656x over previous
#include <cuda_runtime.h>
#include <math.h>
#include <stdint.h>

// Problem constants
#define BD   4
#define LD   8192
#define CD   256
#define HID  2048
#define NS   16
#define EPSL 1e-5f

// ---------------- scratch (__device__ globals; no allocations) ----------------
__device__ float g_Q[BD * LD * CD];
__device__ float g_K[BD * LD * CD];
__device__ float g_V[BD * LD * CD];
__device__ float g_colsum[BD * CD];
__device__ float g_ctxpart[BD * NS * CD * CD];
__device__ float g_ctx[BD * CD * CD];
__device__ float g_Mm[BD * CD * CD];
__device__ float g_attn[BD * LD * CD];
__device__ float g_hidden[BD * LD * HID];
__device__ float g_tmp2[BD * LD * CD];
__device__ float g_srcR[BD * LD * CD];
__device__ float g_tgtR[BD * LD * CD];
__device__ float g_WqR[CD * CD];
__device__ float g_WkR[CD * CD];
__device__ float g_WvR[CD * CD];
__device__ float g_WlR[CD * CD];
__device__ float g_W1R[2 * CD * HID];
__device__ float g_W2R[HID * CD];

// ---------------- helpers ----------------
__device__ __forceinline__ uint32_t f2tf(float f) {
    uint32_t r; asm("cvt.rna.tf32.f32 %0, %1;" : "=r"(r) : "f"(f)); return r;
}
__device__ __forceinline__ float roundtf(float f) {
    return __uint_as_float(f2tf(f));
}
__device__ __forceinline__ void mma_tf32(float* c, const uint32_t* a, const uint32_t* b) {
    asm volatile(
        "mma.sync.aligned.m16n8k8.row.col.f32.tf32.tf32.f32 "
        "{%0,%1,%2,%3}, {%4,%5,%6,%7}, {%8,%9}, {%0,%1,%2,%3};"
        : "+f"(c[0]), "+f"(c[1]), "+f"(c[2]), "+f"(c[3])
        : "r"(a[0]), "r"(a[1]), "r"(a[2]), "r"(a[3]), "r"(b[0]), "r"(b[1]));
}
__device__ __forceinline__ void ldmatrix_x4(uint32_t* r, uint32_t addr) {
    asm volatile("ldmatrix.sync.aligned.m8n8.x4.shared.b16 {%0,%1,%2,%3}, [%4];"
                 : "=r"(r[0]), "=r"(r[1]), "=r"(r[2]), "=r"(r[3]) : "r"(addr));
}
__device__ __forceinline__ void cpasync16(uint32_t dst, const void* src) {
    asm volatile("cp.async.cg.shared.global [%0], [%1], 16;" :: "r"(dst), "l"(src));
}
__device__ __forceinline__ void cp_commit() {
    asm volatile("cp.async.commit_group;" ::: "memory");
}

// ---------------- GEMM tiling ----------------
// CTA tile 128x128x32; 8 warps (2 m x 4 n), warp tile 64x32.
// SMEM word layouts (bank-conflict-free, 16B-chunk preserving):
//   A: word(m,k) = m*32 + (k ^ ((m&7)<<2))     (128 rows x 32 kwords)
//   B: word(k,n) = k*128 + (n ^ ((k&3)<<3))    (32 krows x 128 nwords)
// A fragments fetched with ldmatrix.x4 (one per 16x8 fragment).
#define BM 128
#define BN 128
#define BK 32
#define AWORDS 4096
#define BUFWORDS 8192
#define SMEM_ASYNC (3 * BUFWORDS * 4)    // 98304 (3-stage)
#define SMEM_T     (2 * BUFWORDS * 4)    // 65536 (2-stage, register path)

// ============ cp.async pipelined GEMM (A row-major / concat). All operands
// pre-rounded to tf32 in gmem. EPI: 0 store; 1 +bias; 2 +bias+GELU. RND: round C.
template <int AMODE, int EPI, int RND>
__global__ void __launch_bounds__(256, 2)
tgemm_async(const float* __restrict__ A, const float* __restrict__ A2,
            const float* __restrict__ Bm, const float* __restrict__ bias,
            float* __restrict__ Cmat,
            int Kd, int lda, int ldb, int ldc,
            long long sA, long long sB, long long sC)
{
    extern __shared__ uint32_t sm[];
    const uint32_t sbase = (uint32_t)__cvta_generic_to_shared(sm);
    const int tid = threadIdx.x;
    const int wid = tid >> 5, lane = tid & 31;
    const int wm = wid >> 2, wn = wid & 3;
    const int gid = lane >> 2, tig = lane & 3;

    const int b = blockIdx.z;
    const float* Ab = A + (long long)b * sA;
    const float* Bb = Bm + (long long)b * sB;
    float* Cb = Cmat + (long long)b * sC;
    const int T = Kd / BK;
    const int m0 = blockIdx.y * BM;
    const int n0 = blockIdx.x * BN;

    // ldmatrix per-lane address components
    const uint32_t rbyte = (uint32_t)(lane & 15) * 128;            // row-within-fragment * 32 words
    const uint32_t swl = (uint32_t)((lane & 7) << 2);
    uint32_t kofs[4];
#pragma unroll
    for (int ks = 0; ks < 4; ks++)
        kofs[ks] = (uint32_t)(((ks * 8 + ((lane >> 4) * 4)) ^ swl) * 4);
    const uint32_t awbase = (uint32_t)((wm * 4) * 16) * 128;       // warp m-offset in bytes

    auto issue = [&](int it) {
        const int buf = it % 3;
        const uint32_t Abase = sbase + (uint32_t)buf * (BUFWORDS * 4);
        const uint32_t Bbase = Abase + AWORDS * 4;
        const int kt = it * BK;
#pragma unroll
        for (int j = 0; j < 4; j++) {
            const int idx = tid + 256 * j;
            const int m = idx >> 3, f4 = idx & 7;
            const int kk = kt + f4 * 4;
            const float* src;
            if (AMODE == 2)
                src = (kk < CD) ? &Ab[(size_t)(m0 + m) * CD + kk]
                                : &A2[(size_t)(m0 + m) * CD + (kk - CD)];
            else
                src = &Ab[(size_t)(m0 + m) * lda + kk];
            const uint32_t dw = (uint32_t)(m * 32 + ((f4 * 4) ^ ((m & 7) << 2)));
            cpasync16(Abase + dw * 4, src);
        }
#pragma unroll
        for (int j = 0; j < 4; j++) {
            const int idx = tid + 256 * j;
            const int kr = idx >> 5, nq = idx & 31;
            const float* src = &Bb[(size_t)(kt + kr) * ldb + n0 + nq * 4];
            const uint32_t dw = (uint32_t)(kr * 128 + ((nq * 4) ^ ((kr & 3) << 3)));
            cpasync16(Bbase + dw * 4, src);
        }
        cp_commit();
    };

    float acc[4][4][4];
#pragma unroll
    for (int i = 0; i < 4; i++)
#pragma unroll
        for (int j = 0; j < 4; j++)
#pragma unroll
            for (int e = 0; e < 4; e++) acc[i][j][e] = 0.0f;

    issue(0);
    issue(1);

    for (int it = 0; it < T; ++it) {
        if (it + 1 < T) asm volatile("cp.async.wait_group 1;" ::: "memory");
        else            asm volatile("cp.async.wait_group 0;" ::: "memory");
        __syncthreads();
        if (it + 2 < T) issue(it + 2);

        const int buf = it % 3;
        const uint32_t Abase = sbase + (uint32_t)buf * (BUFWORDS * 4) + awbase + rbyte;
        const uint32_t* Bw = sm + buf * BUFWORDS + AWORDS;
#pragma unroll
        for (int ks = 0; ks < 4; ks++) {
            uint32_t bf[4][2];
            const int kb0 = (ks * 8 + tig) * 128;
#pragma unroll
            for (int jt = 0; jt < 4; jt++) {
                const int nx = ((wn * 4 + jt) * 8 + gid) ^ (tig << 3);
                bf[jt][0] = Bw[kb0 + nx];
                bf[jt][1] = Bw[kb0 + 512 + nx];
            }
#pragma unroll
            for (int i = 0; i < 4; i++) {
                uint32_t af[4];
                ldmatrix_x4(af, Abase + (uint32_t)(i * 2048) + kofs[ks]);
#pragma unroll
                for (int jt = 0; jt < 4; jt++)
                    mma_tf32(acc[i][jt], af, bf[jt]);
            }
        }
    }
    __syncthreads();

    // ---- epilogue: reg -> gmem, fused bias/GELU (+optional tf32 rounding) ----
#pragma unroll
    for (int i = 0; i < 4; i++) {
        const int rbase = m0 + wm * 64 + i * 16 + gid;
#pragma unroll
        for (int j = 0; j < 4; j++) {
            const int cn = n0 + wn * 32 + j * 8 + tig * 2;
            float bia0 = 0.f, bia1 = 0.f;
            if (EPI >= 1) { bia0 = bias[cn]; bia1 = bias[cn + 1]; }
#pragma unroll
            for (int h = 0; h < 2; h++) {
                const int row = rbase + h * 8;
                float v0 = acc[i][j][2 * h + 0] + bia0;
                float v1 = acc[i][j][2 * h + 1] + bia1;
                if (EPI == 2) {
                    v0 = 0.5f * v0 * (1.0f + erff(v0 * 0.70710678118654752f));
                    v1 = 0.5f * v1 * (1.0f + erff(v1 * 0.70710678118654752f));
                }
                if (RND) { v0 = roundtf(v0); v1 = roundtf(v1); }
                float2 out; out.x = v0; out.y = v1;
                *(float2*)&Cb[(size_t)row * ldc + cn] = out;
            }
        }
    }
}

// ============ transposed-A GEMM (register path; operands pre-rounded) ============
template <int RND>
__global__ void __launch_bounds__(256)
tgemm_t(const float* __restrict__ A, const float* __restrict__ Bm,
        float* __restrict__ Cmat,
        int Kd, int nsplit, int lda, int ldb, int ldc,
        long long sA, long long sB, long long sC)
{
    extern __shared__ uint32_t sm[];
    const uint32_t sbase = (uint32_t)__cvta_generic_to_shared(sm);
    const int tid = threadIdx.x;
    const int wid = tid >> 5, lane = tid & 31;
    const int wm = wid >> 2, wn = wid & 3;
    const int gid = lane >> 2, tig = lane & 3;

    const int z = blockIdx.z;
    const int b = z / nsplit;
    const int s = z - b * nsplit;
    const float* Ab = A + (long long)b * sA;
    const float* Bb = Bm + (long long)b * sB;
    float* Cb = Cmat + (long long)z * sC;
    const int kChunk = Kd / nsplit;
    const int k0 = s * kChunk;
    const int T = kChunk / BK;
    const int m0 = blockIdx.y * BM;
    const int n0 = blockIdx.x * BN;

    const uint32_t rbyte = (uint32_t)(lane & 15) * 128;
    const uint32_t swl = (uint32_t)((lane & 7) << 2);
    uint32_t kofs[4];
#pragma unroll
    for (int ks = 0; ks < 4; ks++)
        kofs[ks] = (uint32_t)(((ks * 8 + ((lane >> 4) * 4)) ^ swl) * 4);
    const uint32_t awbase = (uint32_t)((wm * 4) * 16) * 128;

    float4 ra[4], rb[4];

    auto loadTiles = [&](int kt) {
#pragma unroll
        for (int j = 0; j < 4; j++) {
            const int idx = tid + 256 * j;
            const int k = idx >> 5, mq = idx & 31;
            ra[j] = *(const float4*)&Ab[(size_t)(kt + k) * lda + m0 + mq * 4];
        }
#pragma unroll
        for (int j = 0; j < 4; j++) {
            const int idx = tid + 256 * j;
            const int kr = idx >> 5, nq = idx & 31;
            rb[j] = *(const float4*)&Bb[(size_t)(kt + kr) * ldb + n0 + nq * 4];
        }
    };

    auto stsTiles = [&](int buf) {
        uint32_t* Aw = sm + buf * BUFWORDS;
        uint32_t* Bw = Aw + AWORDS;
#pragma unroll
        for (int j = 0; j < 4; j++) {
            const int idx = tid + 256 * j;
            const int k = idx >> 5, mq = idx & 31;
            float v[4] = {ra[j].x, ra[j].y, ra[j].z, ra[j].w};
#pragma unroll
            for (int e = 0; e < 4; e++) {
                const int m = mq * 4 + e;
                Aw[m * 32 + (k ^ ((m & 7) << 2))] = __float_as_uint(v[e]);
            }
        }
#pragma unroll
        for (int j = 0; j < 4; j++) {
            const int idx = tid + 256 * j;
            const int kr = idx >> 5, nq = idx & 31;
            const int base = kr * 128 + ((nq * 4) ^ ((kr & 3) << 3));
            uint4 w;
            w.x = __float_as_uint(rb[j].x); w.y = __float_as_uint(rb[j].y);
            w.z = __float_as_uint(rb[j].z); w.w = __float_as_uint(rb[j].w);
            *(uint4*)&Bw[base] = w;
        }
    };

    float acc[4][4][4];
#pragma unroll
    for (int i = 0; i < 4; i++)
#pragma unroll
        for (int j = 0; j < 4; j++)
#pragma unroll
            for (int e = 0; e < 4; e++) acc[i][j][e] = 0.0f;

    loadTiles(k0);
    stsTiles(0);
    __syncthreads();

    for (int it = 0; it < T; ++it) {
        const int cur = it & 1;
        if (it + 1 < T) loadTiles(k0 + (it + 1) * BK);

        const uint32_t Abase = sbase + (uint32_t)cur * (BUFWORDS * 4) + awbase + rbyte;
        const uint32_t* Bw = sm + cur * BUFWORDS + AWORDS;
#pragma unroll
        for (int ks = 0; ks < 4; ks++) {
            uint32_t bf[4][2];
            const int kb0 = (ks * 8 + tig) * 128;
#pragma unroll
            for (int jt = 0; jt < 4; jt++) {
                const int nx = ((wn * 4 + jt) * 8 + gid) ^ (tig << 3);
                bf[jt][0] = Bw[kb0 + nx];
                bf[jt][1] = Bw[kb0 + 512 + nx];
            }
#pragma unroll
            for (int i = 0; i < 4; i++) {
                uint32_t af[4];
                ldmatrix_x4(af, Abase + (uint32_t)(i * 2048) + kofs[ks]);
#pragma unroll
                for (int jt = 0; jt < 4; jt++)
                    mma_tf32(acc[i][jt], af, bf[jt]);
            }
        }

        if (it + 1 < T) stsTiles((it + 1) & 1);
        __syncthreads();
    }

#pragma unroll
    for (int i = 0; i < 4; i++) {
        const int rbase = m0 + wm * 64 + i * 16 + gid;
#pragma unroll
        for (int j = 0; j < 4; j++) {
            const int cn = n0 + wn * 32 + j * 8 + tig * 2;
#pragma unroll
            for (int h = 0; h < 2; h++) {
                const int row = rbase + h * 8;
                float v0 = acc[i][j][2 * h + 0];
                float v1 = acc[i][j][2 * h + 1];
                if (RND) { v0 = roundtf(v0); v1 = roundtf(v1); }
                float2 out; out.x = v0; out.y = v1;
                *(float2*)&Cb[(size_t)row * ldc + cn] = out;
            }
        }
    }
}

// ---------------- tf32 rounding copies ----------------
__global__ void round2_tf(const float4* __restrict__ a, float4* __restrict__ ao,
                          const float4* __restrict__ b, float4* __restrict__ bo, int n4)
{
    const int i = blockIdx.x * 256 + threadIdx.x;
    if (i >= n4) return;
    const float4* in = blockIdx.y ? b : a;
    float4* out = blockIdx.y ? bo : ao;
    float4 v = in[i];
    v.x = roundtf(v.x); v.y = roundtf(v.y);
    v.z = roundtf(v.z); v.w = roundtf(v.w);
    out[i] = v;
}
__global__ void round4_tf(const float4* __restrict__ p0, float4* __restrict__ o0,
                          const float4* __restrict__ p1, float4* __restrict__ o1,
                          const float4* __restrict__ p2, float4* __restrict__ o2,
                          const float4* __restrict__ p3, float4* __restrict__ o3, int n4)
{
    const int i = blockIdx.x * 256 + threadIdx.x;
    if (i >= n4) return;
    const float4* in; float4* out;
    switch (blockIdx.y) {
        case 0: in = p0; out = o0; break;
        case 1: in = p1; out = o1; break;
        case 2: in = p2; out = o2; break;
        default: in = p3; out = o3; break;
    }
    float4 v = in[i];
    v.x = roundtf(v.x); v.y = roundtf(v.y);
    v.z = roundtf(v.z); v.w = roundtf(v.w);
    out[i] = v;
}
__global__ void round_tf(const float4* __restrict__ in, float4* __restrict__ out, int n4)
{
    const int i = blockIdx.x * 256 + threadIdx.x;
    if (i < n4) {
        float4 v = in[i];
        v.x = roundtf(v.x); v.y = roundtf(v.y);
        v.z = roundtf(v.z); v.w = roundtf(v.w);
        out[i] = v;
    }
}

// ---------------- column softmax of K over token dim (stores rounded exp) ------
__global__ void softmax_cols(float* __restrict__ Kp, float* __restrict__ colsum)
{
    const int bc = blockIdx.x;
    const int b  = bc / (CD / 32);
    const int cg = bc - b * (CD / 32);
    const int tx = threadIdx.x, ty = threadIdx.y;
    const int c  = cg * 32 + tx;
    float* Kb = Kp + (size_t)b * LD * CD + c;

    __shared__ float red[32][33];

    float m = -INFINITY;
    for (int l = ty; l < LD; l += 32)
        m = fmaxf(m, Kb[(size_t)l * CD]);
    red[ty][tx] = m;
    __syncthreads();
    for (int sft = 16; sft > 0; sft >>= 1) {
        if (ty < sft) red[ty][tx] = fmaxf(red[ty][tx], red[ty + sft][tx]);
        __syncthreads();
    }
    m = red[0][tx];
    __syncthreads();

    float sum = 0.0f;
    for (int l = ty; l < LD; l += 32) {
        float e = roundtf(expf(Kb[(size_t)l * CD] - m));
        Kb[(size_t)l * CD] = e;
        sum += e;
    }
    red[ty][tx] = sum;
    __syncthreads();
    for (int sft = 16; sft > 0; sft >>= 1) {
        if (ty < sft) red[ty][tx] += red[ty + sft][tx];
        __syncthreads();
    }
    if (ty == 0) colsum[b * CD + c] = red[0][tx];
}

// ---------------- reduce split-K context partials; fold 1/colsum, round -------
__global__ void ctx_reduce(const float* __restrict__ part,
                           const float* __restrict__ colsum,
                           float* __restrict__ ctx)
{
    const int idx = blockIdx.x * 256 + threadIdx.x;
    const int b  = idx / (CD * CD);
    const int de = idx - b * (CD * CD);
    const int e  = de & (CD - 1);
    float s = 0.0f;
#pragma unroll
    for (int p = 0; p < NS; p++)
        s += part[((size_t)b * NS + p) * CD * CD + de];
    ctx[idx] = roundtf(s / colsum[b * CD + e]);
}

// ---------------- row LayerNorm over C=256 ----------------
__global__ void ln_rows(const float* __restrict__ X, const float* __restrict__ src,
                        const float* __restrict__ gamma, const float* __restrict__ beta,
                        float* __restrict__ out, int addRes, int rnd)
{
    const int row  = blockIdx.x * 8 + threadIdx.y;
    const int lane = threadIdx.x;
    const float* x = X + (size_t)row * CD;

    float v[8];
#pragma unroll
    for (int i = 0; i < 8; i++) v[i] = x[lane + i * 32];

    float s = 0.0f;
#pragma unroll
    for (int i = 0; i < 8; i++) s += v[i];
#pragma unroll
    for (int o = 16; o > 0; o >>= 1) s += __shfl_xor_sync(0xffffffffu, s, o);
    const float mu = s * (1.0f / CD);

    float q = 0.0f;
#pragma unroll
    for (int i = 0; i < 8; i++) { float d = v[i] - mu; q += d * d; }
#pragma unroll
    for (int o = 16; o > 0; o >>= 1) q += __shfl_xor_sync(0xffffffffu, q, o);
    const float rstd = rsqrtf(q * (1.0f / CD) + EPSL);

#pragma unroll
    for (int i = 0; i < 8; i++) {
        const int c = lane + i * 32;
        float y = (v[i] - mu) * rstd * gamma[c] + beta[c];
        if (addRes) y += src[(size_t)row * CD + c];
        if (rnd) y = roundtf(y);
        out[(size_t)row * CD + c] = y;
    }
}

// ---------------- launcher ----------------
extern "C" void kernel_launch(void* const* d_in, const int* in_sizes, int n_in,
                              void* d_out, int out_size)
{
    const float* source = (const float*)d_in[0];
    const float* target = (const float*)d_in[1];
    const float* Wq     = (const float*)d_in[2];
    const float* Wk     = (const float*)d_in[3];
    const float* Wv     = (const float*)d_in[4];
    const float* Wl     = (const float*)d_in[5];
    const float* gamma1 = (const float*)d_in[6];
    const float* beta1  = (const float*)d_in[7];
    const float* W1     = (const float*)d_in[8];
    const float* b1     = (const float*)d_in[9];
    const float* W2     = (const float*)d_in[10];
    const float* b2     = (const float*)d_in[11];
    const float* gamma2 = (const float*)d_in[12];
    const float* beta2  = (const float*)d_in[13];

    float *Q, *Kb, *V, *colsum, *ctxpart, *ctx, *Mm, *attn, *hidden, *tmp2;
    float *srcR, *tgtR, *WqR, *WkR, *WvR, *WlR, *W1R, *W2R;
    cudaGetSymbolAddress((void**)&Q,       g_Q);
    cudaGetSymbolAddress((void**)&Kb,      g_K);
    cudaGetSymbolAddress((void**)&V,       g_V);
    cudaGetSymbolAddress((void**)&colsum,  g_colsum);
    cudaGetSymbolAddress((void**)&ctxpart, g_ctxpart);
    cudaGetSymbolAddress((void**)&ctx,     g_ctx);
    cudaGetSymbolAddress((void**)&Mm,      g_Mm);
    cudaGetSymbolAddress((void**)&attn,    g_attn);
    cudaGetSymbolAddress((void**)&hidden,  g_hidden);
    cudaGetSymbolAddress((void**)&tmp2,    g_tmp2);
    cudaGetSymbolAddress((void**)&srcR,    g_srcR);
    cudaGetSymbolAddress((void**)&tgtR,    g_tgtR);
    cudaGetSymbolAddress((void**)&WqR,     g_WqR);
    cudaGetSymbolAddress((void**)&WkR,     g_WkR);
    cudaGetSymbolAddress((void**)&WvR,     g_WvR);
    cudaGetSymbolAddress((void**)&WlR,     g_WlR);
    cudaGetSymbolAddress((void**)&W1R,     g_W1R);
    cudaGetSymbolAddress((void**)&W2R,     g_W2R);

    cudaFuncSetAttribute(tgemm_async<0, 0, 1>, cudaFuncAttributeMaxDynamicSharedMemorySize, SMEM_ASYNC);
    cudaFuncSetAttribute(tgemm_async<0, 0, 0>, cudaFuncAttributeMaxDynamicSharedMemorySize, SMEM_ASYNC);
    cudaFuncSetAttribute(tgemm_async<2, 2, 1>, cudaFuncAttributeMaxDynamicSharedMemorySize, SMEM_ASYNC);
    cudaFuncSetAttribute(tgemm_async<0, 1, 0>, cudaFuncAttributeMaxDynamicSharedMemorySize, SMEM_ASYNC);
    cudaFuncSetAttribute(tgemm_t<0>,           cudaFuncAttributeMaxDynamicSharedMemorySize, SMEM_T);
    cudaFuncSetAttribute(tgemm_t<1>,           cudaFuncAttributeMaxDynamicSharedMemorySize, SMEM_T);

    const long long LC = (long long)LD * CD;
    const long long CC = (long long)CD * CD;
    const int NLC = BD * LD * CD;

    // 0) tf32-round inputs and weights (4 launches)
    round2_tf<<<dim3((NLC / 4 + 255) / 256, 2), 256>>>((const float4*)source, (float4*)srcR,
                                                       (const float4*)target, (float4*)tgtR, NLC / 4);
    round4_tf<<<dim3((CD * CD / 4 + 255) / 256, 4), 256>>>(
        (const float4*)Wq, (float4*)WqR, (const float4*)Wk, (float4*)WkR,
        (const float4*)Wv, (float4*)WvR, (const float4*)Wl, (float4*)WlR, CD * CD / 4);
    round_tf<<<(2 * CD * HID / 4 + 255) / 256, 256>>>((const float4*)W1, (float4*)W1R, 2 * CD * HID / 4);
    round_tf<<<(HID * CD / 4 + 255) / 256, 256>>>((const float4*)W2, (float4*)W2R, HID * CD / 4);

    // 1-3) Q/K/V projections (M=32768, N=256, K=256)
    tgemm_async<0, 0, 1><<<dim3(2, 256, 1), 256, SMEM_ASYNC>>>(srcR, nullptr, WqR, nullptr, Q,
                                                               CD, CD, CD, CD, 0, 0, 0);
    tgemm_async<0, 0, 0><<<dim3(2, 256, 1), 256, SMEM_ASYNC>>>(tgtR, nullptr, WkR, nullptr, Kb,
                                                               CD, CD, CD, CD, 0, 0, 0);
    tgemm_async<0, 0, 1><<<dim3(2, 256, 1), 256, SMEM_ASYNC>>>(tgtR, nullptr, WvR, nullptr, V,
                                                               CD, CD, CD, CD, 0, 0, 0);

    // 4) column softmax over tokens (stores rounded exp)
    softmax_cols<<<BD * (CD / 32), dim3(32, 32)>>>(Kb, colsum);

    // 5) context partials: ctxpart[b][s] = Q^T(chunk) @ expK
    tgemm_t<0><<<dim3(2, 2, BD * NS), 256, SMEM_T>>>(Q, Kb, ctxpart,
                                                     LD, NS, CD, CD, CD, LC, LC, CC);

    // 6) reduce + 1/colsum (rounds)
    ctx_reduce<<<BD * CD * CD / 256, 256>>>(ctxpart, colsum, ctx);

    // 7) Mm = ctx^T @ Wl (rounds)
    tgemm_t<1><<<dim3(2, 2, BD), 256, SMEM_T>>>(ctx, WlR, Mm,
                                                CD, 1, CD, CD, CD, CC, 0, CC);

    // 8) attn = V @ Mm
    tgemm_async<0, 0, 0><<<dim3(2, 64, BD), 256, SMEM_ASYNC>>>(V, nullptr, Mm, nullptr, attn,
                                                               CD, CD, CD, CD, LC, CC, LC);

    // 9) message = LN(attn), rounded
    ln_rows<<<BD * LD / 8, dim3(32, 8)>>>(attn, nullptr, gamma1, beta1, attn, 0, 1);

    // 10) hidden = gelu([srcR, message] @ W1 + b1), rounded
    tgemm_async<2, 2, 1><<<dim3(16, 256, 1), 256, SMEM_ASYNC>>>(srcR, attn, W1R, b1, hidden,
                                                                2 * CD, CD, HID, HID, 0, 0, 0);

    // 11) tmp2 = hidden @ W2 + b2
    tgemm_async<0, 1, 0><<<dim3(2, 256, 1), 256, SMEM_ASYNC>>>(hidden, nullptr, W2R, b2, tmp2,
                                                               HID, HID, CD, CD, 0, 0, 0);

    // 12) out = source + LN(tmp2)  (original source for residual)
    ln_rows<<<BD * LD / 8, dim3(32, 8)>>>(tmp2, source, gamma2, beta2,
                                          (float*)d_out, 1, 0);
}

// round 8
// speedup vs baseline: 6.9675x; 1.6872x over previous
#include <cuda_runtime.h>
#include <cuda_fp16.h>
#include <math.h>
#include <stdint.h>

// Problem constants
#define BD   4
#define LD   8192
#define CD   256
#define HID  2048
#define NS   16
#define EPSL 1e-5f

// ---------------- scratch (__device__ globals; no allocations) ----------------
__device__ __align__(16) __half h_src[BD * LD * CD];
__device__ __align__(16) __half h_tgt[BD * LD * CD];
__device__ __align__(16) __half h_Wq[CD * CD];
__device__ __align__(16) __half h_Wk[CD * CD];
__device__ __align__(16) __half h_Wv[CD * CD];
__device__ __align__(16) __half h_Wl[CD * CD];
__device__ __align__(16) __half h_W1[2 * CD * HID];
__device__ __align__(16) __half h_W2[HID * CD];
__device__ __align__(16) __half h_Q[BD * LD * CD];
__device__ __align__(16) __half h_K[BD * LD * CD];
__device__ __align__(16) __half h_V[BD * LD * CD];
__device__ __align__(16) __half h_ctx[BD * CD * CD];
__device__ __align__(16) __half h_Mm[BD * CD * CD];
__device__ __align__(16) __half h_attn[BD * LD * CD];
__device__ __align__(16) __half h_hidden[BD * LD * HID];
__device__ float g_ctxpart[BD * NS * CD * CD];
__device__ float g_tmp2[BD * LD * CD];
__device__ float g_colsum[BD * CD];
__device__ float g_pmax[BD * CD * 8];
__device__ float g_psum[BD * CD * 8];

// ---------------- helpers ----------------
__device__ __forceinline__ void mma_f16(float* c, const uint32_t* a, const uint32_t* b) {
    asm volatile(
        "mma.sync.aligned.m16n8k16.row.col.f32.f16.f16.f32 "
        "{%0,%1,%2,%3}, {%4,%5,%6,%7}, {%8,%9}, {%0,%1,%2,%3};"
        : "+f"(c[0]), "+f"(c[1]), "+f"(c[2]), "+f"(c[3])
        : "r"(a[0]), "r"(a[1]), "r"(a[2]), "r"(a[3]), "r"(b[0]), "r"(b[1]));
}
__device__ __forceinline__ void ldsm4(uint32_t* r, uint32_t a) {
    asm volatile("ldmatrix.sync.aligned.m8n8.x4.shared.b16 {%0,%1,%2,%3}, [%4];"
                 : "=r"(r[0]), "=r"(r[1]), "=r"(r[2]), "=r"(r[3]) : "r"(a));
}
__device__ __forceinline__ void ldsm4t(uint32_t* r, uint32_t a) {
    asm volatile("ldmatrix.sync.aligned.m8n8.x4.trans.shared.b16 {%0,%1,%2,%3}, [%4];"
                 : "=r"(r[0]), "=r"(r[1]), "=r"(r[2]), "=r"(r[3]) : "r"(a));
}
__device__ __forceinline__ void cpasync16(uint32_t dst, const void* src) {
    asm volatile("cp.async.cg.shared.global [%0], [%1], 16;" :: "r"(dst), "l"(src));
}
__device__ __forceinline__ void cp_commit() {
    asm volatile("cp.async.commit_group;" ::: "memory");
}

// ---------------- fp16 GEMM tiling ----------------
// CTA tile 128x128x64; 8 warps (2 m x 4 n), warp tile 64x32.
// SMEM (halves), 16B-chunk xor swizzle, all LDSM/STS conflict-free:
//   A: byte(m,k) = m*128 + (((k/8) ^ (m&7))*16 + (k&7)*2)   (128 rows x 64 k)
//   B: byte(k,n) = k*256 + (((n/8) ^ (k&7))*16 + (n&7)*2)   (64 k-rows x 128 n)
// Fragments: A ldmatrix.x4, B ldmatrix.x4.trans.
#define BKH 64
#define ASTG 16384
#define STAGE 32768
#define SMEM_ASYNC (3 * STAGE)    // 98304
#define SMEM_T     (2 * STAGE)    // 65536

// ============ cp.async pipelined fp16 GEMM (A row-major / concat) ============
// EPI: 0 store; 1 +bias; 2 +bias+GELU.  OUTH: 1 = __half out, 0 = float out.
template <int AMODE, int EPI, int OUTH>
__global__ void __launch_bounds__(256, 2)
hgemm_async(const __half* __restrict__ A, const __half* __restrict__ A2,
            const __half* __restrict__ Bm, const float* __restrict__ bias,
            void* __restrict__ Cmat,
            int Kd, int lda, int ldb, int ldc,
            long long sA, long long sB, long long sC)
{
    extern __shared__ char smc[];
    const uint32_t sbase = (uint32_t)__cvta_generic_to_shared(smc);
    const int tid = threadIdx.x;
    const int wid = tid >> 5, lane = tid & 31;
    const int wm = wid >> 2, wn = wid & 3;
    const int gid = lane >> 2, tig = lane & 3;

    const int b = blockIdx.z;
    const __half* Ab = A + (long long)b * sA;
    const __half* Bb = Bm + (long long)b * sB;
    const int T = Kd / BKH;
    const int m0 = blockIdx.y * 128;
    const int n0 = blockIdx.x * 128;

    // fragment address lane constants
    const uint32_t aRow = lane & 15, aSel = lane >> 4, aXor = aRow & 7;
    const uint32_t aByteBase = (uint32_t)(wm * 64 + aRow) * 128;
    const uint32_t r8 = lane & 7, g8 = lane >> 3;
    const uint32_t bRowByte = ((g8 & 1) * 8 + r8) * 256;
    const uint32_t bXor0 = (((uint32_t)wn * 4 + (g8 >> 1)) ^ r8) << 4;
    const uint32_t bXor1 = (((uint32_t)wn * 4 + 2 + (g8 >> 1)) ^ r8) << 4;

    auto issue = [&](int it) {
        const uint32_t Abase = sbase + (uint32_t)(it % 3) * STAGE;
        const uint32_t Bbase = Abase + ASTG;
        const int kt = it * BKH;
#pragma unroll
        for (int j = 0; j < 4; j++) {
            const int idx = tid + 256 * j;
            const int m = idx >> 3, f = idx & 7;
            const int kk = kt + f * 8;
            const __half* src;
            if (AMODE == 2)
                src = (kk < CD) ? Ab + (size_t)(m0 + m) * CD + kk
                                : A2 + (size_t)(m0 + m) * CD + (kk - CD);
            else
                src = Ab + (size_t)(m0 + m) * lda + kk;
            cpasync16(Abase + (uint32_t)(m * 128 + ((f ^ (m & 7)) << 4)), src);
        }
#pragma unroll
        for (int j = 0; j < 4; j++) {
            const int idx = tid + 256 * j;
            const int k = idx >> 4, c = idx & 15;
            const __half* src = Bb + (size_t)(kt + k) * ldb + n0 + c * 8;
            cpasync16(Bbase + (uint32_t)(k * 256 + ((c ^ (k & 7)) << 4)), src);
        }
        cp_commit();
    };

    float acc[4][4][4];
#pragma unroll
    for (int i = 0; i < 4; i++)
#pragma unroll
        for (int j = 0; j < 4; j++)
#pragma unroll
            for (int e = 0; e < 4; e++) acc[i][j][e] = 0.0f;

    issue(0);
    if (T > 1) issue(1);

    for (int it = 0; it < T; ++it) {
        if (it + 1 < T) asm volatile("cp.async.wait_group 1;" ::: "memory");
        else            asm volatile("cp.async.wait_group 0;" ::: "memory");
        __syncthreads();
        if (it + 2 < T) issue(it + 2);

        const uint32_t Ab0 = sbase + (uint32_t)(it % 3) * STAGE + aByteBase;
        const uint32_t Bb0 = sbase + (uint32_t)(it % 3) * STAGE + ASTG + bRowByte;
#pragma unroll
        for (int st = 0; st < 4; st++) {
            uint32_t b0r[4], b1r[4];
            ldsm4t(b0r, Bb0 + st * 4096 + bXor0);
            ldsm4t(b1r, Bb0 + st * 4096 + bXor1);
#pragma unroll
            for (int i = 0; i < 4; i++) {
                uint32_t af[4];
                ldsm4(af, Ab0 + i * 2048 + ((((uint32_t)st * 2 + aSel) ^ aXor) << 4));
                mma_f16(acc[i][0], af, b0r);
                mma_f16(acc[i][1], af, b0r + 2);
                mma_f16(acc[i][2], af, b1r);
                mma_f16(acc[i][3], af, b1r + 2);
            }
        }
    }

    // ---- epilogue: reg -> gmem, fused bias/GELU, fp16 or fp32 out ----
#pragma unroll
    for (int i = 0; i < 4; i++) {
        const int rbase = m0 + wm * 64 + i * 16 + gid;
#pragma unroll
        for (int j = 0; j < 4; j++) {
            const int cn = n0 + wn * 32 + j * 8 + tig * 2;
            float bia0 = 0.f, bia1 = 0.f;
            if (EPI >= 1) { bia0 = bias[cn]; bia1 = bias[cn + 1]; }
#pragma unroll
            for (int h = 0; h < 2; h++) {
                const int row = rbase + h * 8;
                float v0 = acc[i][j][2 * h + 0] + bia0;
                float v1 = acc[i][j][2 * h + 1] + bia1;
                if (EPI == 2) {
                    v0 = 0.5f * v0 * (1.0f + erff(v0 * 0.70710678118654752f));
                    v1 = 0.5f * v1 * (1.0f + erff(v1 * 0.70710678118654752f));
                }
                if (OUTH) {
                    __half2 hv = __floats2half2_rn(v0, v1);
                    *(__half2*)((__half*)Cmat + (long long)b * sC + (size_t)row * ldc + cn) = hv;
                } else {
                    float2 fv; fv.x = v0; fv.y = v1;
                    *(float2*)((float*)Cmat + (long long)b * sC + (size_t)row * ldc + cn) = fv;
                }
            }
        }
    }
}

// ============ transposed-A fp16 GEMM (register-staged, 2-buffer) ============
template <int OUTH>
__global__ void __launch_bounds__(256)
hgemm_t(const __half* __restrict__ A, const __half* __restrict__ Bm,
        void* __restrict__ Cmat,
        int Kd, int nsplit, int lda, int ldb, int ldc,
        long long sA, long long sB, long long sC)
{
    extern __shared__ char smc[];
    const uint32_t sbase = (uint32_t)__cvta_generic_to_shared(smc);
    const int tid = threadIdx.x;
    const int wid = tid >> 5, lane = tid & 31;
    const int wm = wid >> 2, wn = wid & 3;
    const int gid = lane >> 2, tig = lane & 3;

    const int z = blockIdx.z;
    const int b = z / nsplit;
    const int s = z - b * nsplit;
    const __half* Ab = A + (long long)b * sA;
    const __half* Bb = Bm + (long long)b * sB;
    const int kChunk = Kd / nsplit;
    const int k0 = s * kChunk;
    const int T = kChunk / BKH;
    const int m0 = blockIdx.y * 128;
    const int n0 = blockIdx.x * 128;

    const uint32_t aRow = lane & 15, aSel = lane >> 4, aXor = aRow & 7;
    const uint32_t aByteBase = (uint32_t)(wm * 64 + aRow) * 128;
    const uint32_t r8 = lane & 7, g8 = lane >> 3;
    const uint32_t bRowByte = ((g8 & 1) * 8 + r8) * 256;
    const uint32_t bXor0 = (((uint32_t)wn * 4 + (g8 >> 1)) ^ r8) << 4;
    const uint32_t bXor1 = (((uint32_t)wn * 4 + 2 + (g8 >> 1)) ^ r8) << 4;

    float4 ra[4], rb[4];

    auto loadTiles = [&](int kt) {
#pragma unroll
        for (int j = 0; j < 4; j++) {
            const int idx = tid + 256 * j;
            const int k = idx >> 4, mq = idx & 15;
            ra[j] = *(const float4*)(Ab + (size_t)(kt + k) * lda + m0 + mq * 8);
        }
#pragma unroll
        for (int j = 0; j < 4; j++) {
            const int idx = tid + 256 * j;
            const int k = idx >> 4, c = idx & 15;
            rb[j] = *(const float4*)(Bb + (size_t)(kt + k) * ldb + n0 + c * 8);
        }
    };

    auto stsTiles = [&](int buf) {
        char* base = smc + buf * STAGE;
#pragma unroll
        for (int j = 0; j < 4; j++) {
            const int idx = tid + 256 * j;
            const int k = idx >> 4, mq = idx & 15;
            const __half* hp = (const __half*)&ra[j];
#pragma unroll
            for (int e = 0; e < 8; e++) {
                const int m = mq * 8 + e;
                *(__half*)(base + m * 128 + (((k >> 3) ^ (m & 7)) << 4) + (k & 7) * 2) = hp[e];
            }
        }
#pragma unroll
        for (int j = 0; j < 4; j++) {
            const int idx = tid + 256 * j;
            const int k = idx >> 4, c = idx & 15;
            *(uint4*)(base + ASTG + k * 256 + ((c ^ (k & 7)) << 4)) = *(const uint4*)&rb[j];
        }
    };

    float acc[4][4][4];
#pragma unroll
    for (int i = 0; i < 4; i++)
#pragma unroll
        for (int j = 0; j < 4; j++)
#pragma unroll
            for (int e = 0; e < 4; e++) acc[i][j][e] = 0.0f;

    loadTiles(k0);
    stsTiles(0);
    __syncthreads();

    for (int it = 0; it < T; ++it) {
        const int cur = it & 1;
        if (it + 1 < T) loadTiles(k0 + (it + 1) * BKH);

        const uint32_t Ab0 = sbase + (uint32_t)cur * STAGE + aByteBase;
        const uint32_t Bb0 = sbase + (uint32_t)cur * STAGE + ASTG + bRowByte;
#pragma unroll
        for (int st = 0; st < 4; st++) {
            uint32_t b0r[4], b1r[4];
            ldsm4t(b0r, Bb0 + st * 4096 + bXor0);
            ldsm4t(b1r, Bb0 + st * 4096 + bXor1);
#pragma unroll
            for (int i = 0; i < 4; i++) {
                uint32_t af[4];
                ldsm4(af, Ab0 + i * 2048 + ((((uint32_t)st * 2 + aSel) ^ aXor) << 4));
                mma_f16(acc[i][0], af, b0r);
                mma_f16(acc[i][1], af, b0r + 2);
                mma_f16(acc[i][2], af, b1r);
                mma_f16(acc[i][3], af, b1r + 2);
            }
        }

        if (it + 1 < T) stsTiles((it + 1) & 1);
        __syncthreads();
    }

#pragma unroll
    for (int i = 0; i < 4; i++) {
        const int rbase = m0 + wm * 64 + i * 16 + gid;
#pragma unroll
        for (int j = 0; j < 4; j++) {
            const int cn = n0 + wn * 32 + j * 8 + tig * 2;
#pragma unroll
            for (int h = 0; h < 2; h++) {
                const int row = rbase + h * 8;
                float v0 = acc[i][j][2 * h + 0];
                float v1 = acc[i][j][2 * h + 1];
                if (OUTH) {
                    __half2 hv = __floats2half2_rn(v0, v1);
                    *(__half2*)((__half*)Cmat + (long long)z * sC + (size_t)row * ldc + cn) = hv;
                } else {
                    float2 fv; fv.x = v0; fv.y = v1;
                    *(float2*)((float*)Cmat + (long long)z * sC + (size_t)row * ldc + cn) = fv;
                }
            }
        }
    }
}

// ---------------- fp32 -> fp16 converts ----------------
__global__ void cvt2h(const float4* __restrict__ a, __half* __restrict__ ao,
                      const float4* __restrict__ b, __half* __restrict__ bo, int n8)
{
    const int i = blockIdx.x * 256 + threadIdx.x;
    if (i >= n8) return;
    const float4* in = blockIdx.y ? b : a;
    __half* out = blockIdx.y ? bo : ao;
    float4 u = in[2 * i], v = in[2 * i + 1];
    __align__(16) __half2 hh[4];
    hh[0] = __floats2half2_rn(u.x, u.y);
    hh[1] = __floats2half2_rn(u.z, u.w);
    hh[2] = __floats2half2_rn(v.x, v.y);
    hh[3] = __floats2half2_rn(v.z, v.w);
    *(uint4*)(out + (size_t)i * 8) = *(const uint4*)hh;
}
__global__ void cvt6h(const float4* p0, __half* o0, const float4* p1, __half* o1,
                      const float4* p2, __half* o2, const float4* p3, __half* o3,
                      const float4* p4, __half* o4, const float4* p5, __half* o5,
                      int nw, int n1, int n2)   // nw: Wq..Wl size/8, n1: W1/8, n2: W2/8
{
    const int i = blockIdx.x * 256 + threadIdx.x;
    const int y = blockIdx.y;
    const float4* in; __half* out; int n;
    switch (y) {
        case 0: in = p0; out = o0; n = nw; break;
        case 1: in = p1; out = o1; n = nw; break;
        case 2: in = p2; out = o2; n = nw; break;
        case 3: in = p3; out = o3; n = nw; break;
        case 4: in = p4; out = o4; n = n1; break;
        default: in = p5; out = o5; n = n2; break;
    }
    if (i >= n) return;
    float4 u = in[2 * i], v = in[2 * i + 1];
    __align__(16) __half2 hh[4];
    hh[0] = __floats2half2_rn(u.x, u.y);
    hh[1] = __floats2half2_rn(u.z, u.w);
    hh[2] = __floats2half2_rn(v.x, v.y);
    hh[3] = __floats2half2_rn(v.z, v.w);
    *(uint4*)(out + (size_t)i * 8) = *(const uint4*)hh;
}

// ---------------- column softmax (3-pass, split-L, fp16 K in place) ----------
__global__ void colmax_k(const __half* __restrict__ Kp, float* __restrict__ pmax)
{
    const int b = blockIdx.x >> 3, cg = blockIdx.x & 7;
    const int seg = blockIdx.y;
    const int tx = threadIdx.x, ty = threadIdx.y;
    const int c = cg * 32 + tx;
    const __half* base = Kp + (size_t)b * LD * CD + c;
    __shared__ float red[32][33];
    float m = -INFINITY;
    const int l0 = seg * (LD / 8);
    for (int l = l0 + ty; l < l0 + LD / 8; l += 32)
        m = fmaxf(m, __half2float(base[(size_t)l * CD]));
    red[ty][tx] = m;
    __syncthreads();
    for (int s = 16; s > 0; s >>= 1) {
        if (ty < s) red[ty][tx] = fmaxf(red[ty][tx], red[ty + s][tx]);
        __syncthreads();
    }
    if (ty == 0) pmax[((size_t)b * CD + c) * 8 + seg] = red[0][tx];
}
__global__ void expsum_k(__half* __restrict__ Kp, const float* __restrict__ pmax,
                         float* __restrict__ psum)
{
    const int b = blockIdx.x >> 3, cg = blockIdx.x & 7;
    const int seg = blockIdx.y;
    const int tx = threadIdx.x, ty = threadIdx.y;
    const int c = cg * 32 + tx;
    __half* base = Kp + (size_t)b * LD * CD + c;
    __shared__ float red[32][33];
    float m = -INFINITY;
#pragma unroll
    for (int s = 0; s < 8; s++) m = fmaxf(m, pmax[((size_t)b * CD + c) * 8 + s]);
    float sum = 0.0f;
    const int l0 = seg * (LD / 8);
    for (int l = l0 + ty; l < l0 + LD / 8; l += 32) {
        float e = expf(__half2float(base[(size_t)l * CD]) - m);
        base[(size_t)l * CD] = __float2half_rn(e);
        sum += e;
    }
    red[ty][tx] = sum;
    __syncthreads();
    for (int s = 16; s > 0; s >>= 1) {
        if (ty < s) red[ty][tx] += red[ty + s][tx];
        __syncthreads();
    }
    if (ty == 0) psum[((size_t)b * CD + c) * 8 + seg] = red[0][tx];
}
__global__ void colsum_k(const float* __restrict__ psum, float* __restrict__ colsum)
{
    const int i = blockIdx.x * 256 + threadIdx.x;
    if (i >= BD * CD) return;
    float s = 0.0f;
#pragma unroll
    for (int p = 0; p < 8; p++) s += psum[(size_t)i * 8 + p];
    colsum[i] = s;
}

// ---------------- reduce split-K ctx partials; fold 1/colsum; fp16 out -------
__global__ void ctx_reduce(const float* __restrict__ part,
                           const float* __restrict__ colsum,
                           __half* __restrict__ ctx)
{
    const int idx = blockIdx.x * 256 + threadIdx.x;
    const int b = idx / (CD * CD);
    const int de = idx - b * (CD * CD);
    const int e = de & (CD - 1);
    float s = 0.0f;
#pragma unroll
    for (int p = 0; p < NS; p++)
        s += part[((size_t)b * NS + p) * CD * CD + de];
    ctx[idx] = __float2half_rn(s / colsum[b * CD + e]);
}

// ---------------- row LayerNorm over C=256 ----------------
template <int INH, int OUTH>
__global__ void ln_rows(const void* __restrict__ X, const float* __restrict__ src,
                        const float* __restrict__ gamma, const float* __restrict__ beta,
                        void* __restrict__ out, int addRes)
{
    const int row = blockIdx.x * 8 + threadIdx.y;
    const int lane = threadIdx.x;

    float v[8];
#pragma unroll
    for (int i = 0; i < 8; i++) {
        const int c = lane + i * 32;
        v[i] = INH ? __half2float(((const __half*)X)[(size_t)row * CD + c])
                   : ((const float*)X)[(size_t)row * CD + c];
    }
    float s = 0.0f;
#pragma unroll
    for (int i = 0; i < 8; i++) s += v[i];
#pragma unroll
    for (int o = 16; o > 0; o >>= 1) s += __shfl_xor_sync(0xffffffffu, s, o);
    const float mu = s * (1.0f / CD);
    float q = 0.0f;
#pragma unroll
    for (int i = 0; i < 8; i++) { float d = v[i] - mu; q += d * d; }
#pragma unroll
    for (int o = 16; o > 0; o >>= 1) q += __shfl_xor_sync(0xffffffffu, q, o);
    const float rstd = rsqrtf(q * (1.0f / CD) + EPSL);
#pragma unroll
    for (int i = 0; i < 8; i++) {
        const int c = lane + i * 32;
        float y = (v[i] - mu) * rstd * gamma[c] + beta[c];
        if (addRes) y += src[(size_t)row * CD + c];
        if (OUTH) ((__half*)out)[(size_t)row * CD + c] = __float2half_rn(y);
        else      ((float*)out)[(size_t)row * CD + c] = y;
    }
}

// ---------------- launcher ----------------
extern "C" void kernel_launch(void* const* d_in, const int* in_sizes, int n_in,
                              void* d_out, int out_size)
{
    const float* source = (const float*)d_in[0];
    const float* target = (const float*)d_in[1];
    const float* Wq     = (const float*)d_in[2];
    const float* Wk     = (const float*)d_in[3];
    const float* Wv     = (const float*)d_in[4];
    const float* Wl     = (const float*)d_in[5];
    const float* gamma1 = (const float*)d_in[6];
    const float* beta1  = (const float*)d_in[7];
    const float* W1     = (const float*)d_in[8];
    const float* b1     = (const float*)d_in[9];
    const float* W2     = (const float*)d_in[10];
    const float* b2     = (const float*)d_in[11];
    const float* gamma2 = (const float*)d_in[12];
    const float* beta2  = (const float*)d_in[13];

    __half *srcH, *tgtH, *WqH, *WkH, *WvH, *WlH, *W1H, *W2H;
    __half *QH, *KH, *VH, *ctxH, *MmH, *attnH, *hidH;
    float *ctxpart, *tmp2, *colsum, *pmax, *psum;
    cudaGetSymbolAddress((void**)&srcH, h_src);
    cudaGetSymbolAddress((void**)&tgtH, h_tgt);
    cudaGetSymbolAddress((void**)&WqH,  h_Wq);
    cudaGetSymbolAddress((void**)&WkH,  h_Wk);
    cudaGetSymbolAddress((void**)&WvH,  h_Wv);
    cudaGetSymbolAddress((void**)&WlH,  h_Wl);
    cudaGetSymbolAddress((void**)&W1H,  h_W1);
    cudaGetSymbolAddress((void**)&W2H,  h_W2);
    cudaGetSymbolAddress((void**)&QH,   h_Q);
    cudaGetSymbolAddress((void**)&KH,   h_K);
    cudaGetSymbolAddress((void**)&VH,   h_V);
    cudaGetSymbolAddress((void**)&ctxH, h_ctx);
    cudaGetSymbolAddress((void**)&MmH,  h_Mm);
    cudaGetSymbolAddress((void**)&attnH, h_attn);
    cudaGetSymbolAddress((void**)&hidH, h_hidden);
    cudaGetSymbolAddress((void**)&ctxpart, g_ctxpart);
    cudaGetSymbolAddress((void**)&tmp2, g_tmp2);
    cudaGetSymbolAddress((void**)&colsum, g_colsum);
    cudaGetSymbolAddress((void**)&pmax, g_pmax);
    cudaGetSymbolAddress((void**)&psum, g_psum);

    cudaFuncSetAttribute(hgemm_async<0, 0, 1>, cudaFuncAttributeMaxDynamicSharedMemorySize, SMEM_ASYNC);
    cudaFuncSetAttribute(hgemm_async<2, 2, 1>, cudaFuncAttributeMaxDynamicSharedMemorySize, SMEM_ASYNC);
    cudaFuncSetAttribute(hgemm_async<0, 1, 0>, cudaFuncAttributeMaxDynamicSharedMemorySize, SMEM_ASYNC);
    cudaFuncSetAttribute(hgemm_t<0>, cudaFuncAttributeMaxDynamicSharedMemorySize, SMEM_T);
    cudaFuncSetAttribute(hgemm_t<1>, cudaFuncAttributeMaxDynamicSharedMemorySize, SMEM_T);

    const long long LC = (long long)LD * CD;
    const long long CC = (long long)CD * CD;
    const int NLC = BD * LD * CD;

    // 0) fp16 converts
    cvt2h<<<dim3(NLC / 8 / 256, 2), 256>>>((const float4*)source, srcH,
                                           (const float4*)target, tgtH, NLC / 8);
    cvt6h<<<dim3(2 * CD * HID / 8 / 256, 6), 256>>>(
        (const float4*)Wq, WqH, (const float4*)Wk, WkH,
        (const float4*)Wv, WvH, (const float4*)Wl, WlH,
        (const float4*)W1, W1H, (const float4*)W2, W2H,
        CD * CD / 8, 2 * CD * HID / 8, HID * CD / 8);

    // 1-3) Q/K/V projections (M=32768, N=256, K=256), fp16 out
    hgemm_async<0, 0, 1><<<dim3(2, 256, 1), 256, SMEM_ASYNC>>>(srcH, nullptr, WqH, nullptr, QH,
                                                               CD, CD, CD, CD, 0, 0, 0);
    hgemm_async<0, 0, 1><<<dim3(2, 256, 1), 256, SMEM_ASYNC>>>(tgtH, nullptr, WkH, nullptr, KH,
                                                               CD, CD, CD, CD, 0, 0, 0);
    hgemm_async<0, 0, 1><<<dim3(2, 256, 1), 256, SMEM_ASYNC>>>(tgtH, nullptr, WvH, nullptr, VH,
                                                               CD, CD, CD, CD, 0, 0, 0);

    // 4) column softmax over tokens (split-L, fp16 in place)
    colmax_k<<<dim3(32, 8), dim3(32, 32)>>>(KH, pmax);
    expsum_k<<<dim3(32, 8), dim3(32, 32)>>>(KH, pmax, psum);
    colsum_k<<<(BD * CD + 255) / 256, 256>>>(psum, colsum);

    // 5) context partials: ctxpart[b][s] = Q^T(chunk) @ expK  (fp32 out)
    hgemm_t<0><<<dim3(2, 2, BD * NS), 256, SMEM_T>>>(QH, KH, ctxpart,
                                                     LD, NS, CD, CD, CD, LC, LC, CC);

    // 6) reduce + 1/colsum -> fp16 ctx
    ctx_reduce<<<BD * CD * CD / 256, 256>>>(ctxpart, colsum, ctxH);

    // 7) Mm = ctx^T @ Wl (fp16 out)
    hgemm_t<1><<<dim3(2, 2, BD), 256, SMEM_T>>>(ctxH, WlH, MmH,
                                                CD, 1, CD, CD, CD, CC, 0, CC);

    // 8) attn = V @ Mm (fp16 out)
    hgemm_async<0, 0, 1><<<dim3(2, 64, BD), 256, SMEM_ASYNC>>>(VH, nullptr, MmH, nullptr, attnH,
                                                               CD, CD, CD, CD, LC, CC, LC);

    // 9) message = LN(attn), fp16 in/out in place
    ln_rows<1, 1><<<BD * LD / 8, dim3(32, 8)>>>(attnH, nullptr, gamma1, beta1, attnH, 0);

    // 10) hidden = gelu([srcH, message] @ W1 + b1), fp16 out
    hgemm_async<2, 2, 1><<<dim3(16, 256, 1), 256, SMEM_ASYNC>>>(srcH, attnH, W1H, b1, hidH,
                                                                2 * CD, CD, HID, HID, 0, 0, 0);

    // 11) tmp2 = hidden @ W2 + b2 (fp32 out)
    hgemm_async<0, 1, 0><<<dim3(2, 256, 1), 256, SMEM_ASYNC>>>(hidH, nullptr, W2H, b2, tmp2,
                                                               HID, HID, CD, CD, 0, 0, 0);

    // 12) out = source + LN(tmp2), fp32
    ln_rows<0, 0><<<BD * LD / 8, dim3(32, 8)>>>(tmp2, source, gamma2, beta2,
                                                (float*)d_out, 1);
}

// round 9
// speedup vs baseline: 7.0047x; 1.0053x over previous
#include <cuda_runtime.h>
#include <cuda_fp16.h>
#include <math.h>
#include <stdint.h>

// Problem constants
#define BD   4
#define LD   8192
#define CD   256
#define HID  2048
#define NS   16
#define EPSL 1e-5f

// ---------------- scratch (__device__ globals; no allocations) ----------------
__device__ __align__(16) __half h_src[BD * LD * CD];
__device__ __align__(16) __half h_tgt[BD * LD * CD];
__device__ __align__(16) __half h_Wq[CD * CD];
__device__ __align__(16) __half h_Wkv[CD * 2 * CD];     // interleaved [k][Wk|Wv]
__device__ __align__(16) __half h_Wl[CD * CD];
__device__ __align__(16) __half h_W1[2 * CD * HID];
__device__ __align__(16) __half h_W2[HID * CD];
__device__ __align__(16) __half h_Q[BD * LD * CD];
__device__ __align__(16) __half h_KV[BD * LD * 2 * CD]; // cols 0-255 K, 256-511 V
__device__ __align__(16) __half h_ctx[BD * CD * CD];
__device__ __align__(16) __half h_Mm[BD * CD * CD];
__device__ __align__(16) __half h_attn[BD * LD * CD];
__device__ __align__(16) __half h_hidden[BD * LD * HID];
__device__ float g_ctxpart[BD * NS * CD * CD];
__device__ float g_tmp2[BD * LD * CD];
__device__ float g_colsum[BD * CD];
__device__ float g_pmax[BD * CD * 8];
__device__ float g_psum[BD * CD * 8];

// ---------------- helpers ----------------
__device__ __forceinline__ void mma_f16(float* c, const uint32_t* a, const uint32_t* b) {
    asm volatile(
        "mma.sync.aligned.m16n8k16.row.col.f32.f16.f16.f32 "
        "{%0,%1,%2,%3}, {%4,%5,%6,%7}, {%8,%9}, {%0,%1,%2,%3};"
        : "+f"(c[0]), "+f"(c[1]), "+f"(c[2]), "+f"(c[3])
        : "r"(a[0]), "r"(a[1]), "r"(a[2]), "r"(a[3]), "r"(b[0]), "r"(b[1]));
}
__device__ __forceinline__ void ldsm4(uint32_t* r, uint32_t a) {
    asm volatile("ldmatrix.sync.aligned.m8n8.x4.shared.b16 {%0,%1,%2,%3}, [%4];"
                 : "=r"(r[0]), "=r"(r[1]), "=r"(r[2]), "=r"(r[3]) : "r"(a));
}
__device__ __forceinline__ void ldsm4t(uint32_t* r, uint32_t a) {
    asm volatile("ldmatrix.sync.aligned.m8n8.x4.trans.shared.b16 {%0,%1,%2,%3}, [%4];"
                 : "=r"(r[0]), "=r"(r[1]), "=r"(r[2]), "=r"(r[3]) : "r"(a));
}
__device__ __forceinline__ void cpasync16(uint32_t dst, const void* src) {
    asm volatile("cp.async.cg.shared.global [%0], [%1], 16;" :: "r"(dst), "l"(src));
}
__device__ __forceinline__ void cp_commit() {
    asm volatile("cp.async.commit_group;" ::: "memory");
}

// ---------------- fp16 GEMM tiling ----------------
// CTA tile 128x128x64; 8 warps (2 m x 4 n), warp tile 64x32.
// SMEM (halves), 16B-chunk xor swizzle, all LDSM/STS conflict-free:
//   A: byte(m,k) = m*128 + (((k/8) ^ (m&7))*16 + (k&7)*2)   (128 rows x 64 k)
//   B: byte(k,n) = k*256 + (((n/8) ^ (k&7))*16 + (n&7)*2)   (64 k-rows x 128 n)
// Fragments: A ldmatrix.x4 (batched per k-step), B ldmatrix.x4.trans
// (double-buffered across k-steps).
#define BKH 64
#define ASTG 16384
#define STAGE 32768
#define SMEM_ASYNC (3 * STAGE)    // 98304
#define SMEM_T     (2 * STAGE)    // 65536

// Pipelined compute over one 64-k smem stage (8 warps). bf double-buffered.
#define COMPUTE_STAGE(Ab0, Bb0)                                                 \
    do {                                                                        \
        uint32_t bf[2][8];                                                      \
        ldsm4t(bf[0],     (Bb0) + bXor0);                                       \
        ldsm4t(bf[0] + 4, (Bb0) + bXor1);                                       \
        _Pragma("unroll")                                                       \
        for (int st = 0; st < 4; st++) {                                        \
            uint32_t af[4][4];                                                  \
            _Pragma("unroll")                                                   \
            for (int i = 0; i < 4; i++)                                         \
                ldsm4(af[i], (Ab0) + i * 2048 +                                 \
                      ((((uint32_t)st * 2 + aSel) ^ aXor) << 4));               \
            if (st < 3) {                                                       \
                ldsm4t(bf[(st + 1) & 1],     (Bb0) + (st + 1) * 4096 + bXor0);  \
                ldsm4t(bf[(st + 1) & 1] + 4, (Bb0) + (st + 1) * 4096 + bXor1);  \
            }                                                                   \
            const uint32_t* bc = bf[st & 1];                                    \
            _Pragma("unroll")                                                   \
            for (int i = 0; i < 4; i++) {                                       \
                mma_f16(acc[i][0], af[i], bc);                                  \
                mma_f16(acc[i][1], af[i], bc + 2);                              \
                mma_f16(acc[i][2], af[i], bc + 4);                              \
                mma_f16(acc[i][3], af[i], bc + 6);                              \
            }                                                                   \
        }                                                                       \
    } while (0)

// ============ cp.async pipelined fp16 GEMM (A row-major / concat) ============
// EPI: 0 store; 1 +bias; 2 +bias+GELU.  OUTH: 1 = __half out, 0 = float out.
template <int AMODE, int EPI, int OUTH>
__global__ void __launch_bounds__(256, 2)
hgemm_async(const __half* __restrict__ A, const __half* __restrict__ A2,
            const __half* __restrict__ Bm, const float* __restrict__ bias,
            void* __restrict__ Cmat,
            int Kd, int lda, int ldb, int ldc,
            long long sA, long long sB, long long sC)
{
    extern __shared__ char smc[];
    const uint32_t sbase = (uint32_t)__cvta_generic_to_shared(smc);
    const int tid = threadIdx.x;
    const int wid = tid >> 5, lane = tid & 31;
    const int wm = wid >> 2, wn = wid & 3;
    const int gid = lane >> 2, tig = lane & 3;

    const int b = blockIdx.z;
    const __half* Ab = A + (long long)b * sA;
    const __half* Bb = Bm + (long long)b * sB;
    const int T = Kd / BKH;
    const int m0 = blockIdx.y * 128;
    const int n0 = blockIdx.x * 128;

    const uint32_t aRow = lane & 15, aSel = lane >> 4, aXor = aRow & 7;
    const uint32_t aByteBase = (uint32_t)(wm * 64 + aRow) * 128;
    const uint32_t r8 = lane & 7, g8 = lane >> 3;
    const uint32_t bRowByte = ((g8 & 1) * 8 + r8) * 256;
    const uint32_t bXor0 = (((uint32_t)wn * 4 + (g8 >> 1)) ^ r8) << 4;
    const uint32_t bXor1 = (((uint32_t)wn * 4 + 2 + (g8 >> 1)) ^ r8) << 4;

    auto issue = [&](int it) {
        const uint32_t Abase = sbase + (uint32_t)(it % 3) * STAGE;
        const uint32_t Bbase = Abase + ASTG;
        const int kt = it * BKH;
#pragma unroll
        for (int j = 0; j < 4; j++) {
            const int idx = tid + 256 * j;
            const int m = idx >> 3, f = idx & 7;
            const int kk = kt + f * 8;
            const __half* src;
            if (AMODE == 2)
                src = (kk < CD) ? Ab + (size_t)(m0 + m) * CD + kk
                                : A2 + (size_t)(m0 + m) * CD + (kk - CD);
            else
                src = Ab + (size_t)(m0 + m) * lda + kk;
            cpasync16(Abase + (uint32_t)(m * 128 + ((f ^ (m & 7)) << 4)), src);
        }
#pragma unroll
        for (int j = 0; j < 4; j++) {
            const int idx = tid + 256 * j;
            const int k = idx >> 4, c = idx & 15;
            const __half* src = Bb + (size_t)(kt + k) * ldb + n0 + c * 8;
            cpasync16(Bbase + (uint32_t)(k * 256 + ((c ^ (k & 7)) << 4)), src);
        }
        cp_commit();
    };

    float acc[4][4][4];
#pragma unroll
    for (int i = 0; i < 4; i++)
#pragma unroll
        for (int j = 0; j < 4; j++)
#pragma unroll
            for (int e = 0; e < 4; e++) acc[i][j][e] = 0.0f;

    issue(0);
    if (T > 1) issue(1);

    for (int it = 0; it < T; ++it) {
        if (it + 1 < T) asm volatile("cp.async.wait_group 1;" ::: "memory");
        else            asm volatile("cp.async.wait_group 0;" ::: "memory");
        __syncthreads();
        if (it + 2 < T) issue(it + 2);

        const uint32_t Ab0 = sbase + (uint32_t)(it % 3) * STAGE + aByteBase;
        const uint32_t Bb0 = sbase + (uint32_t)(it % 3) * STAGE + ASTG + bRowByte;
        COMPUTE_STAGE(Ab0, Bb0);
    }

    // ---- epilogue ----
#pragma unroll
    for (int i = 0; i < 4; i++) {
        const int rbase = m0 + wm * 64 + i * 16 + gid;
#pragma unroll
        for (int j = 0; j < 4; j++) {
            const int cn = n0 + wn * 32 + j * 8 + tig * 2;
            float bia0 = 0.f, bia1 = 0.f;
            if (EPI >= 1) { bia0 = bias[cn]; bia1 = bias[cn + 1]; }
#pragma unroll
            for (int h = 0; h < 2; h++) {
                const int row = rbase + h * 8;
                float v0 = acc[i][j][2 * h + 0] + bia0;
                float v1 = acc[i][j][2 * h + 1] + bia1;
                if (EPI == 2) {
                    v0 = 0.5f * v0 * (1.0f + erff(v0 * 0.70710678118654752f));
                    v1 = 0.5f * v1 * (1.0f + erff(v1 * 0.70710678118654752f));
                }
                if (OUTH) {
                    __half2 hv = __floats2half2_rn(v0, v1);
                    *(__half2*)((__half*)Cmat + (long long)b * sC + (size_t)row * ldc + cn) = hv;
                } else {
                    float2 fv; fv.x = v0; fv.y = v1;
                    *(float2*)((float*)Cmat + (long long)b * sC + (size_t)row * ldc + cn) = fv;
                }
            }
        }
    }
}

// ============ transposed-A fp16 GEMM (register-staged, 2-buffer) ============
template <int OUTH>
__global__ void __launch_bounds__(256)
hgemm_t(const __half* __restrict__ A, const __half* __restrict__ Bm,
        void* __restrict__ Cmat,
        int Kd, int nsplit, int lda, int ldb, int ldc,
        long long sA, long long sB, long long sC)
{
    extern __shared__ char smc[];
    const uint32_t sbase = (uint32_t)__cvta_generic_to_shared(smc);
    const int tid = threadIdx.x;
    const int wid = tid >> 5, lane = tid & 31;
    const int wm = wid >> 2, wn = wid & 3;
    const int gid = lane >> 2, tig = lane & 3;

    const int z = blockIdx.z;
    const int b = z / nsplit;
    const int s = z - b * nsplit;
    const __half* Ab = A + (long long)b * sA;
    const __half* Bb = Bm + (long long)b * sB;
    const int kChunk = Kd / nsplit;
    const int k0 = s * kChunk;
    const int T = kChunk / BKH;
    const int m0 = blockIdx.y * 128;
    const int n0 = blockIdx.x * 128;

    const uint32_t aRow = lane & 15, aSel = lane >> 4, aXor = aRow & 7;
    const uint32_t aByteBase = (uint32_t)(wm * 64 + aRow) * 128;
    const uint32_t r8 = lane & 7, g8 = lane >> 3;
    const uint32_t bRowByte = ((g8 & 1) * 8 + r8) * 256;
    const uint32_t bXor0 = (((uint32_t)wn * 4 + (g8 >> 1)) ^ r8) << 4;
    const uint32_t bXor1 = (((uint32_t)wn * 4 + 2 + (g8 >> 1)) ^ r8) << 4;

    float4 ra[4], rb[4];

    auto loadTiles = [&](int kt) {
#pragma unroll
        for (int j = 0; j < 4; j++) {
            const int idx = tid + 256 * j;
            const int k = idx >> 4, mq = idx & 15;
            ra[j] = *(const float4*)(Ab + (size_t)(kt + k) * lda + m0 + mq * 8);
        }
#pragma unroll
        for (int j = 0; j < 4; j++) {
            const int idx = tid + 256 * j;
            const int k = idx >> 4, c = idx & 15;
            rb[j] = *(const float4*)(Bb + (size_t)(kt + k) * ldb + n0 + c * 8);
        }
    };

    auto stsTiles = [&](int buf) {
        char* base = smc + buf * STAGE;
#pragma unroll
        for (int j = 0; j < 4; j++) {
            const int idx = tid + 256 * j;
            const int k = idx >> 4, mq = idx & 15;
            const __half* hp = (const __half*)&ra[j];
#pragma unroll
            for (int e = 0; e < 8; e++) {
                const int m = mq * 8 + e;
                *(__half*)(base + m * 128 + (((k >> 3) ^ (m & 7)) << 4) + (k & 7) * 2) = hp[e];
            }
        }
#pragma unroll
        for (int j = 0; j < 4; j++) {
            const int idx = tid + 256 * j;
            const int k = idx >> 4, c = idx & 15;
            *(uint4*)(base + ASTG + k * 256 + ((c ^ (k & 7)) << 4)) = *(const uint4*)&rb[j];
        }
    };

    float acc[4][4][4];
#pragma unroll
    for (int i = 0; i < 4; i++)
#pragma unroll
        for (int j = 0; j < 4; j++)
#pragma unroll
            for (int e = 0; e < 4; e++) acc[i][j][e] = 0.0f;

    loadTiles(k0);
    stsTiles(0);
    __syncthreads();

    for (int it = 0; it < T; ++it) {
        const int cur = it & 1;
        if (it + 1 < T) loadTiles(k0 + (it + 1) * BKH);

        const uint32_t Ab0 = sbase + (uint32_t)cur * STAGE + aByteBase;
        const uint32_t Bb0 = sbase + (uint32_t)cur * STAGE + ASTG + bRowByte;
        COMPUTE_STAGE(Ab0, Bb0);

        if (it + 1 < T) stsTiles((it + 1) & 1);
        __syncthreads();
    }

#pragma unroll
    for (int i = 0; i < 4; i++) {
        const int rbase = m0 + wm * 64 + i * 16 + gid;
#pragma unroll
        for (int j = 0; j < 4; j++) {
            const int cn = n0 + wn * 32 + j * 8 + tig * 2;
#pragma unroll
            for (int h = 0; h < 2; h++) {
                const int row = rbase + h * 8;
                float v0 = acc[i][j][2 * h + 0];
                float v1 = acc[i][j][2 * h + 1];
                if (OUTH) {
                    __half2 hv = __floats2half2_rn(v0, v1);
                    *(__half2*)((__half*)Cmat + (long long)z * sC + (size_t)row * ldc + cn) = hv;
                } else {
                    float2 fv; fv.x = v0; fv.y = v1;
                    *(float2*)((float*)Cmat + (long long)z * sC + (size_t)row * ldc + cn) = fv;
                }
            }
        }
    }
}

// ---------------- fp32 -> fp16 converts ----------------
__device__ __forceinline__ void cvt8(const float4* in, __half* out, size_t i) {
    float4 u = in[2 * i], v = in[2 * i + 1];
    __align__(16) __half2 hh[4];
    hh[0] = __floats2half2_rn(u.x, u.y);
    hh[1] = __floats2half2_rn(u.z, u.w);
    hh[2] = __floats2half2_rn(v.x, v.y);
    hh[3] = __floats2half2_rn(v.z, v.w);
    *(uint4*)(out + i * 8) = *(const uint4*)hh;
}
__global__ void cvt2h(const float4* __restrict__ a, __half* __restrict__ ao,
                      const float4* __restrict__ b, __half* __restrict__ bo, int n8)
{
    const int i = blockIdx.x * 256 + threadIdx.x;
    if (i >= n8) return;
    cvt8(blockIdx.y ? b : a, blockIdx.y ? bo : ao, i);
}
__global__ void cvt4h(const float4* p0, __half* o0, const float4* p1, __half* o1,
                      const float4* p2, __half* o2, const float4* p3, __half* o3,
                      int n0, int n1, int n2, int n3)
{
    const int i = blockIdx.x * 256 + threadIdx.x;
    const float4* in; __half* out; int n;
    switch (blockIdx.y) {
        case 0: in = p0; out = o0; n = n0; break;
        case 1: in = p1; out = o1; n = n1; break;
        case 2: in = p2; out = o2; n = n2; break;
        default: in = p3; out = o3; n = n3; break;
    }
    if (i >= n) return;
    cvt8(in, out, i);
}
// interleave Wk|Wv into [k][512]
__global__ void cvt_kv(const float4* __restrict__ Wk, const float4* __restrict__ Wv,
                       __half* __restrict__ out, int n8)
{
    const int i = blockIdx.x * 256 + threadIdx.x;
    if (i >= n8) return;
    const float4* in = blockIdx.y ? Wv : Wk;
    const int ofs = blockIdx.y ? CD : 0;
    const int k = (i * 8) / CD, n = (i * 8) % CD;
    float4 u = in[2 * i], v = in[2 * i + 1];
    __align__(16) __half2 hh[4];
    hh[0] = __floats2half2_rn(u.x, u.y);
    hh[1] = __floats2half2_rn(u.z, u.w);
    hh[2] = __floats2half2_rn(v.x, v.y);
    hh[3] = __floats2half2_rn(v.z, v.w);
    *(uint4*)(out + (size_t)k * 512 + ofs + n) = *(const uint4*)hh;
}

// ---------------- column softmax (3-pass, split-L, in KV buffer, stride 512) --
__global__ void colmax_k(const __half* __restrict__ KV, float* __restrict__ pmax)
{
    const int b = blockIdx.x >> 3, cg = blockIdx.x & 7;
    const int seg = blockIdx.y;
    const int tx = threadIdx.x, ty = threadIdx.y;
    const int c = cg * 32 + tx;
    const __half* base = KV + (size_t)b * LD * 512 + c;
    __shared__ float red[32][33];
    float m = -INFINITY;
    const int l0 = seg * (LD / 8);
    for (int l = l0 + ty; l < l0 + LD / 8; l += 32)
        m = fmaxf(m, __half2float(base[(size_t)l * 512]));
    red[ty][tx] = m;
    __syncthreads();
    for (int s = 16; s > 0; s >>= 1) {
        if (ty < s) red[ty][tx] = fmaxf(red[ty][tx], red[ty + s][tx]);
        __syncthreads();
    }
    if (ty == 0) pmax[((size_t)b * CD + c) * 8 + seg] = red[0][tx];
}
__global__ void expsum_k(__half* __restrict__ KV, const float* __restrict__ pmax,
                         float* __restrict__ psum)
{
    const int b = blockIdx.x >> 3, cg = blockIdx.x & 7;
    const int seg = blockIdx.y;
    const int tx = threadIdx.x, ty = threadIdx.y;
    const int c = cg * 32 + tx;
    __half* base = KV + (size_t)b * LD * 512 + c;
    __shared__ float red[32][33];
    float m = -INFINITY;
#pragma unroll
    for (int s = 0; s < 8; s++) m = fmaxf(m, pmax[((size_t)b * CD + c) * 8 + s]);
    float sum = 0.0f;
    const int l0 = seg * (LD / 8);
    for (int l = l0 + ty; l < l0 + LD / 8; l += 32) {
        float e = expf(__half2float(base[(size_t)l * 512]) - m);
        base[(size_t)l * 512] = __float2half_rn(e);
        sum += e;
    }
    red[ty][tx] = sum;
    __syncthreads();
    for (int s = 16; s > 0; s >>= 1) {
        if (ty < s) red[ty][tx] += red[ty + s][tx];
        __syncthreads();
    }
    if (ty == 0) psum[((size_t)b * CD + c) * 8 + seg] = red[0][tx];
}
__global__ void colsum_k(const float* __restrict__ psum, float* __restrict__ colsum)
{
    const int i = blockIdx.x * 256 + threadIdx.x;
    if (i >= BD * CD) return;
    float s = 0.0f;
#pragma unroll
    for (int p = 0; p < 8; p++) s += psum[(size_t)i * 8 + p];
    colsum[i] = s;
}

// ---------------- reduce split-K ctx partials; fold 1/colsum; fp16 out -------
__global__ void ctx_reduce(const float* __restrict__ part,
                           const float* __restrict__ colsum,
                           __half* __restrict__ ctx)
{
    const int idx = blockIdx.x * 256 + threadIdx.x;
    const int b = idx / (CD * CD);
    const int de = idx - b * (CD * CD);
    const int e = de & (CD - 1);
    float s = 0.0f;
#pragma unroll
    for (int p = 0; p < NS; p++)
        s += part[((size_t)b * NS + p) * CD * CD + de];
    ctx[idx] = __float2half_rn(s / colsum[b * CD + e]);
}

// ---------------- row LayerNorm over C=256 ----------------
template <int INH, int OUTH>
__global__ void ln_rows(const void* __restrict__ X, const float* __restrict__ src,
                        const float* __restrict__ gamma, const float* __restrict__ beta,
                        void* __restrict__ out, int addRes)
{
    const int row = blockIdx.x * 8 + threadIdx.y;
    const int lane = threadIdx.x;

    float v[8];
#pragma unroll
    for (int i = 0; i < 8; i++) {
        const int c = lane + i * 32;
        v[i] = INH ? __half2float(((const __half*)X)[(size_t)row * CD + c])
                   : ((const float*)X)[(size_t)row * CD + c];
    }
    float s = 0.0f;
#pragma unroll
    for (int i = 0; i < 8; i++) s += v[i];
#pragma unroll
    for (int o = 16; o > 0; o >>= 1) s += __shfl_xor_sync(0xffffffffu, s, o);
    const float mu = s * (1.0f / CD);
    float q = 0.0f;
#pragma unroll
    for (int i = 0; i < 8; i++) { float d = v[i] - mu; q += d * d; }
#pragma unroll
    for (int o = 16; o > 0; o >>= 1) q += __shfl_xor_sync(0xffffffffu, q, o);
    const float rstd = rsqrtf(q * (1.0f / CD) + EPSL);
#pragma unroll
    for (int i = 0; i < 8; i++) {
        const int c = lane + i * 32;
        float y = (v[i] - mu) * rstd * gamma[c] + beta[c];
        if (addRes) y += src[(size_t)row * CD + c];
        if (OUTH) ((__half*)out)[(size_t)row * CD + c] = __float2half_rn(y);
        else      ((float*)out)[(size_t)row * CD + c] = y;
    }
}

// ---------------- launcher ----------------
extern "C" void kernel_launch(void* const* d_in, const int* in_sizes, int n_in,
                              void* d_out, int out_size)
{
    const float* source = (const float*)d_in[0];
    const float* target = (const float*)d_in[1];
    const float* Wq     = (const float*)d_in[2];
    const float* Wk     = (const float*)d_in[3];
    const float* Wv     = (const float*)d_in[4];
    const float* Wl     = (const float*)d_in[5];
    const float* gamma1 = (const float*)d_in[6];
    const float* beta1  = (const float*)d_in[7];
    const float* W1     = (const float*)d_in[8];
    const float* b1     = (const float*)d_in[9];
    const float* W2     = (const float*)d_in[10];
    const float* b2     = (const float*)d_in[11];
    const float* gamma2 = (const float*)d_in[12];
    const float* beta2  = (const float*)d_in[13];

    __half *srcH, *tgtH, *WqH, *WkvH, *WlH, *W1H, *W2H;
    __half *QH, *KVH, *ctxH, *MmH, *attnH, *hidH;
    float *ctxpart, *tmp2, *colsum, *pmax, *psum;
    cudaGetSymbolAddress((void**)&srcH, h_src);
    cudaGetSymbolAddress((void**)&tgtH, h_tgt);
    cudaGetSymbolAddress((void**)&WqH,  h_Wq);
    cudaGetSymbolAddress((void**)&WkvH, h_Wkv);
    cudaGetSymbolAddress((void**)&WlH,  h_Wl);
    cudaGetSymbolAddress((void**)&W1H,  h_W1);
    cudaGetSymbolAddress((void**)&W2H,  h_W2);
    cudaGetSymbolAddress((void**)&QH,   h_Q);
    cudaGetSymbolAddress((void**)&KVH,  h_KV);
    cudaGetSymbolAddress((void**)&ctxH, h_ctx);
    cudaGetSymbolAddress((void**)&MmH,  h_Mm);
    cudaGetSymbolAddress((void**)&attnH, h_attn);
    cudaGetSymbolAddress((void**)&hidH, h_hidden);
    cudaGetSymbolAddress((void**)&ctxpart, g_ctxpart);
    cudaGetSymbolAddress((void**)&tmp2, g_tmp2);
    cudaGetSymbolAddress((void**)&colsum, g_colsum);
    cudaGetSymbolAddress((void**)&pmax, g_pmax);
    cudaGetSymbolAddress((void**)&psum, g_psum);

    cudaFuncSetAttribute(hgemm_async<0, 0, 1>, cudaFuncAttributeMaxDynamicSharedMemorySize, SMEM_ASYNC);
    cudaFuncSetAttribute(hgemm_async<2, 2, 1>, cudaFuncAttributeMaxDynamicSharedMemorySize, SMEM_ASYNC);
    cudaFuncSetAttribute(hgemm_async<0, 1, 0>, cudaFuncAttributeMaxDynamicSharedMemorySize, SMEM_ASYNC);
    cudaFuncSetAttribute(hgemm_t<0>, cudaFuncAttributeMaxDynamicSharedMemorySize, SMEM_T);
    cudaFuncSetAttribute(hgemm_t<1>, cudaFuncAttributeMaxDynamicSharedMemorySize, SMEM_T);

    const long long LC = (long long)LD * CD;
    const long long L5 = (long long)LD * 512;
    const long long CC = (long long)CD * CD;
    const int NLC = BD * LD * CD;

    // 0) fp16 converts
    cvt2h<<<dim3(NLC / 8 / 256, 2), 256>>>((const float4*)source, srcH,
                                           (const float4*)target, tgtH, NLC / 8);
    cvt4h<<<dim3(2 * CD * HID / 8 / 256, 4), 256>>>(
        (const float4*)Wq, WqH, (const float4*)Wl, WlH,
        (const float4*)W1, W1H, (const float4*)W2, W2H,
        CD * CD / 8, CD * CD / 8, 2 * CD * HID / 8, HID * CD / 8);
    cvt_kv<<<dim3(CD * CD / 8 / 256, 2), 256>>>((const float4*)Wk, (const float4*)Wv,
                                                WkvH, CD * CD / 8);

    // 1) Q projection (M=32768, N=256, K=256)
    hgemm_async<0, 0, 1><<<dim3(2, 256, 1), 256, SMEM_ASYNC>>>(srcH, nullptr, WqH, nullptr, QH,
                                                               CD, CD, CD, CD, 0, 0, 0);
    // 2) K|V fused projection (M=32768, N=512, K=256)
    hgemm_async<0, 0, 1><<<dim3(4, 256, 1), 256, SMEM_ASYNC>>>(tgtH, nullptr, WkvH, nullptr, KVH,
                                                               CD, CD, 512, 512, 0, 0, 0);

    // 3) column softmax over tokens (K region of KV, stride 512)
    colmax_k<<<dim3(32, 8), dim3(32, 32)>>>(KVH, pmax);
    expsum_k<<<dim3(32, 8), dim3(32, 32)>>>(KVH, pmax, psum);
    colsum_k<<<(BD * CD + 255) / 256, 256>>>(psum, colsum);

    // 4) context partials: ctxpart[b][s] = Q^T(chunk) @ expK  (fp32 out)
    hgemm_t<0><<<dim3(2, 2, BD * NS), 256, SMEM_T>>>(QH, KVH, ctxpart,
                                                     LD, NS, CD, 512, CD, LC, L5, CC);

    // 5) reduce + 1/colsum -> fp16 ctx
    ctx_reduce<<<BD * CD * CD / 256, 256>>>(ctxpart, colsum, ctxH);

    // 6) Mm = ctx^T @ Wl (fp16 out)
    hgemm_t<1><<<dim3(2, 2, BD), 256, SMEM_T>>>(ctxH, WlH, MmH,
                                                CD, 1, CD, CD, CD, CC, 0, CC);

    // 7) attn = V @ Mm (V = KV cols 256-511; fp16 out)
    hgemm_async<0, 0, 1><<<dim3(2, 64, BD), 256, SMEM_ASYNC>>>(KVH + CD, nullptr, MmH, nullptr, attnH,
                                                               CD, 512, CD, CD, L5, CC, LC);

    // 8) message = LN(attn), fp16 in/out in place
    ln_rows<1, 1><<<BD * LD / 8, dim3(32, 8)>>>(attnH, nullptr, gamma1, beta1, attnH, 0);

    // 9) hidden = gelu([srcH, message] @ W1 + b1), fp16 out
    hgemm_async<2, 2, 1><<<dim3(16, 256, 1), 256, SMEM_ASYNC>>>(srcH, attnH, W1H, b1, hidH,
                                                                2 * CD, CD, HID, HID, 0, 0, 0);

    // 10) tmp2 = hidden @ W2 + b2 (fp32 out)
    hgemm_async<0, 1, 0><<<dim3(2, 256, 1), 256, SMEM_ASYNC>>>(hidH, nullptr, W2H, b2, tmp2,
                                                               HID, HID, CD, CD, 0, 0, 0);

    // 11) out = source + LN(tmp2), fp32
    ln_rows<0, 0><<<BD * LD / 8, dim3(32, 8)>>>(tmp2, source, gamma2, beta2,
                                                (float*)d_out, 1);
}